// round 2
// baseline (speedup 1.0000x reference)
#include <cuda_runtime.h>
#include <cuda_bf16.h>
#include <math.h>

// Problem constants
#define BATCH   4
#define SEQ     2048
#define HDIM    1024          // model dim (K for projections, N for output proj)
#define NHEADS  16
#define HEADD   64
#define MROWS   (BATCH * SEQ) // 8192

// ---------------- scratch (static device globals; no runtime allocation) ----
__device__ float g_Pq[(size_t)MROWS * HDIM];   // phi(q)
__device__ float g_Pk[(size_t)MROWS * HDIM];   // phi(k)
__device__ float g_V [(size_t)MROWS * HDIM];   // v
__device__ float g_B [(size_t)MROWS * NHEADS]; // sigmoid(beta proj)
__device__ float g_Y [(size_t)MROWS * HDIM];   // scan output

// ---------------- fp32 SGEMM: C[M,N] = A[M,K] @ W[N,K]^T + bias, epilogue ---
// EPI 0: none; EPI 1: phi(x) = x>0 ? x+1 : exp(x)
#define BM 128
#define BN 128
#define BK 16
#define TM 8
#define TN 8

template<int EPI>
__global__ __launch_bounds__(256)
void sgemm_nt(int M, int N, int K,
              const float* __restrict__ A,
              const float* __restrict__ W,
              const float* __restrict__ bias,
              float* __restrict__ C)
{
    __shared__ float As[BK][BM];
    __shared__ float Bs[BK][BN];

    const int tid  = threadIdx.x;
    const int crow = blockIdx.y * BM;
    const int ccol = blockIdx.x * BN;

    const int tRow = tid / (BN / TN);   // 0..15
    const int tCol = tid % (BN / TN);   // 0..15

    // loader mapping: 64 rows per pass, 4 floats (float4) per thread
    const int ldRow = tid >> 2;         // 0..63
    const int ldCol = (tid & 3) * 4;    // 0,4,8,12

    const float* Aptr = A + (size_t)crow * K;
    const float* Wptr = W + (size_t)ccol * K;

    float acc[TM][TN];
#pragma unroll
    for (int i = 0; i < TM; i++)
#pragma unroll
        for (int j = 0; j < TN; j++) acc[i][j] = 0.f;

    float regM[TM], regN[TN];

    for (int k0 = 0; k0 < K; k0 += BK) {
#pragma unroll
        for (int r = 0; r < BM; r += 64) {
            float4 t = *(const float4*)(Aptr + (size_t)(ldRow + r) * K + k0 + ldCol);
            As[ldCol + 0][ldRow + r] = t.x;
            As[ldCol + 1][ldRow + r] = t.y;
            As[ldCol + 2][ldRow + r] = t.z;
            As[ldCol + 3][ldRow + r] = t.w;
        }
#pragma unroll
        for (int r = 0; r < BN; r += 64) {
            float4 t = *(const float4*)(Wptr + (size_t)(ldRow + r) * K + k0 + ldCol);
            Bs[ldCol + 0][ldRow + r] = t.x;
            Bs[ldCol + 1][ldRow + r] = t.y;
            Bs[ldCol + 2][ldRow + r] = t.z;
            Bs[ldCol + 3][ldRow + r] = t.w;
        }
        __syncthreads();

#pragma unroll
        for (int kk = 0; kk < BK; kk++) {
#pragma unroll
            for (int i = 0; i < TM; i++) regM[i] = As[kk][tRow * TM + i];
#pragma unroll
            for (int j = 0; j < TN; j++) regN[j] = Bs[kk][tCol * TN + j];
#pragma unroll
            for (int i = 0; i < TM; i++)
#pragma unroll
                for (int j = 0; j < TN; j++)
                    acc[i][j] = fmaf(regM[i], regN[j], acc[i][j]);
        }
        __syncthreads();
    }

    // epilogue
#pragma unroll
    for (int i = 0; i < TM; i++) {
        const int row = crow + tRow * TM + i;
#pragma unroll
        for (int j = 0; j < TN; j++) {
            const int col = ccol + tCol * TN + j;
            float c = acc[i][j] + bias[col];
            if (EPI == 1) c = (c > 0.f) ? (c + 1.f) : expf(c);
            C[(size_t)row * N + col] = c;
        }
    }
}

// ---------------- beta projection: Bsig[M,16] = sigmoid(A @ Wb^T + bb) ------
// block: 256 threads handles 16 rows; K chunked by 64 through shared memory.
__global__ __launch_bounds__(256)
void beta_kernel(const float* __restrict__ A,
                 const float* __restrict__ Wb,
                 const float* __restrict__ bb,
                 float* __restrict__ Bsig,
                 int M, int K)
{
    __shared__ float Ash[16][65];
    __shared__ float Wsh[16][65];

    const int tid = threadIdx.x;
    const int m0  = blockIdx.x * 16;

    const int ldRow  = tid / 16;        // 0..15
    const int ldCol4 = (tid % 16) * 4;  // 0..60

    const int tm = tid / 16;            // row within block
    const int n  = tid % 16;            // head

    float acc = 0.f;

    for (int k0 = 0; k0 < K; k0 += 64) {
        {
            float4 t = *(const float4*)(A + (size_t)(m0 + ldRow) * K + k0 + ldCol4);
            Ash[ldRow][ldCol4 + 0] = t.x;
            Ash[ldRow][ldCol4 + 1] = t.y;
            Ash[ldRow][ldCol4 + 2] = t.z;
            Ash[ldRow][ldCol4 + 3] = t.w;
        }
        {
            float4 t = *(const float4*)(Wb + (size_t)ldRow * K + k0 + ldCol4);
            Wsh[ldRow][ldCol4 + 0] = t.x;
            Wsh[ldRow][ldCol4 + 1] = t.y;
            Wsh[ldRow][ldCol4 + 2] = t.z;
            Wsh[ldRow][ldCol4 + 3] = t.w;
        }
        __syncthreads();
#pragma unroll
        for (int k = 0; k < 64; k++)
            acc = fmaf(Ash[tm][k], Wsh[n][k], acc);
        __syncthreads();
    }

    acc += bb[n];
    Bsig[(size_t)(m0 + tm) * NHEADS + n] = 1.f / (1.f + expf(-acc));
}

// ---------------- delta-rule diagonal-state scan ----------------------------
// One block per (batch, head): 64 threads, one per state dim.
// s <- s + b*(v - s*pk)*pk ;  y = s*pq   (s starts at 0)
__global__ __launch_bounds__(64)
void scan_kernel(const float* __restrict__ Pq,
                 const float* __restrict__ Pk,
                 const float* __restrict__ Vb,
                 const float* __restrict__ Bsig,
                 float* __restrict__ Y)
{
    const int bh = blockIdx.x;
    const int b  = bh >> 4;
    const int h  = bh & 15;
    const int d  = threadIdx.x;

    const size_t base = (size_t)b * SEQ * HDIM + (size_t)h * HEADD + d;
    const float* pk = Pk   + base;
    const float* pq = Pq   + base;
    const float* vv = Vb   + base;
    float*       y  = Y    + base;
    const float* bp = Bsig + (size_t)b * SEQ * NHEADS + h;

    float s = 0.f;

    // software-pipelined: prefetch t+1 while computing t
    float cpk = pk[0], cpq = pq[0], cv = vv[0], cb = bp[0];

#pragma unroll 4
    for (int t = 0; t < SEQ; t++) {
        float npk = 0.f, npq = 0.f, nv = 0.f, nb = 0.f;
        if (t + 1 < SEQ) {
            const size_t o = (size_t)(t + 1) * HDIM;
            npk = pk[o]; npq = pq[o]; nv = vv[o];
            nb  = bp[(size_t)(t + 1) * NHEADS];
        }
        // s = s + cb*(cv - s*cpk)*cpk
        s = fmaf(cb * (cv - s * cpk), cpk, s);
        y[(size_t)t * HDIM] = s * cpq;

        cpk = npk; cpq = npq; cv = nv; cb = nb;
    }
}

// ---------------- launch -----------------------------------------------------
extern "C" void kernel_launch(void* const* d_in, const int* in_sizes, int n_in,
                              void* d_out, int out_size)
{
    const float* query = (const float*)d_in[0];
    const float* key   = (const float*)d_in[1];
    const float* value = (const float*)d_in[2];
    const float* beta  = (const float*)d_in[3];
    const float* Wq    = (const float*)d_in[4];
    const float* bq    = (const float*)d_in[5];
    const float* Wk    = (const float*)d_in[6];
    const float* bk    = (const float*)d_in[7];
    const float* Wv    = (const float*)d_in[8];
    const float* bv    = (const float*)d_in[9];
    const float* Wb    = (const float*)d_in[10];
    const float* bb    = (const float*)d_in[11];
    const float* Wo    = (const float*)d_in[12];
    const float* bo    = (const float*)d_in[13];
    float* out = (float*)d_out;

    float *pPq, *pPk, *pV, *pB, *pY;
    cudaGetSymbolAddress((void**)&pPq, g_Pq);
    cudaGetSymbolAddress((void**)&pPk, g_Pk);
    cudaGetSymbolAddress((void**)&pV,  g_V);
    cudaGetSymbolAddress((void**)&pB,  g_B);
    cudaGetSymbolAddress((void**)&pY,  g_Y);

    dim3 grid(HDIM / BN, MROWS / BM);   // (8, 64)
    dim3 block(256);

    // q, k projections with fused phi
    sgemm_nt<1><<<grid, block>>>(MROWS, HDIM, HDIM, query, Wq, bq, pPq);
    sgemm_nt<1><<<grid, block>>>(MROWS, HDIM, HDIM, key,   Wk, bk, pPk);
    // v projection
    sgemm_nt<0><<<grid, block>>>(MROWS, HDIM, HDIM, value, Wv, bv, pV);
    // beta projection + sigmoid
    beta_kernel<<<MROWS / 16, 256>>>(beta, Wb, bb, pB, MROWS, HDIM);
    // diagonal delta-rule scan
    scan_kernel<<<BATCH * NHEADS, 64>>>(pPq, pPk, pV, pB, pY);
    // output projection
    sgemm_nt<0><<<grid, block>>>(MROWS, HDIM, HDIM, pY, Wo, bo, out);
}

// round 6
// speedup vs baseline: 2.0740x; 2.0740x over previous
#include <cuda_runtime.h>
#include <cuda_bf16.h>
#include <math.h>
#include <stdint.h>

#define BATCH   4
#define SEQ     2048
#define HDIM    1024
#define NHEADS  16
#define MROWS   8192

// ---------------- scratch (device globals; no runtime allocation) -----------
__device__ __nv_bfloat16 g_Ahi[(size_t)MROWS * HDIM];
__device__ __nv_bfloat16 g_Alo[(size_t)MROWS * HDIM];
__device__ __nv_bfloat16 g_Wqhi[(size_t)HDIM * HDIM];
__device__ __nv_bfloat16 g_Wqlo[(size_t)HDIM * HDIM];
__device__ __nv_bfloat16 g_Wkhi[(size_t)HDIM * HDIM];
__device__ __nv_bfloat16 g_Wklo[(size_t)HDIM * HDIM];
__device__ __nv_bfloat16 g_Wvhi[(size_t)HDIM * HDIM];
__device__ __nv_bfloat16 g_Wvlo[(size_t)HDIM * HDIM];
__device__ __nv_bfloat16 g_Wohi[(size_t)HDIM * HDIM];
__device__ __nv_bfloat16 g_Wolo[(size_t)HDIM * HDIM];
__device__ __nv_bfloat16 g_Wbhi[(size_t)NHEADS * HDIM];
__device__ __nv_bfloat16 g_Wblo[(size_t)NHEADS * HDIM];
__device__ float g_Pq[(size_t)MROWS * HDIM];
__device__ float g_Pk[(size_t)MROWS * HDIM];
__device__ float g_V [(size_t)MROWS * HDIM];
__device__ float g_B [(size_t)MROWS * NHEADS];

// ---------------- baseline-PTX helpers --------------------------------------
__device__ __forceinline__ uint32_t smem_u32(const void* p) {
    uint32_t a;
    asm("{ .reg .u64 t; cvta.to.shared.u64 t, %1; cvt.u32.u64 %0, t; }" : "=r"(a) : "l"(p));
    return a;
}
__device__ __forceinline__ void cp16(uint32_t dst, const void* src) {
    asm volatile("cp.async.cg.shared.global [%0], [%1], 16;\n" :: "r"(dst), "l"(src) : "memory");
}
__device__ __forceinline__ void cp_commit() {
    asm volatile("cp.async.commit_group;\n" ::: "memory");
}
template<int N> __device__ __forceinline__ void cp_wait() {
    asm volatile("cp.async.wait_group %0;\n" :: "n"(N) : "memory");
}
__device__ __forceinline__ void ldsm_x4(uint32_t& r0, uint32_t& r1, uint32_t& r2, uint32_t& r3,
                                        uint32_t addr) {
    asm volatile("ldmatrix.sync.aligned.m8n8.x4.shared.b16 {%0,%1,%2,%3}, [%4];"
                 : "=r"(r0), "=r"(r1), "=r"(r2), "=r"(r3) : "r"(addr));
}
__device__ __forceinline__ void mma_bf16(float* c, const uint32_t* a, const uint32_t* b) {
    asm volatile(
        "mma.sync.aligned.m16n8k16.row.col.f32.bf16.bf16.f32 "
        "{%0,%1,%2,%3}, {%4,%5,%6,%7}, {%8,%9}, {%0,%1,%2,%3};"
        : "+f"(c[0]), "+f"(c[1]), "+f"(c[2]), "+f"(c[3])
        : "r"(a[0]), "r"(a[1]), "r"(a[2]), "r"(a[3]), "r"(b[0]), "r"(b[1]));
}

// ---------------- split conversion: fp32 -> bf16 hi + bf16 lo ---------------
__global__ __launch_bounds__(256)
void conv_split(const float* __restrict__ x, __nv_bfloat16* __restrict__ hi,
                __nv_bfloat16* __restrict__ lo, int n4)
{
    int i = blockIdx.x * blockDim.x + threadIdx.x;
    if (i >= n4) return;
    float4 v = ((const float4*)x)[i];
    __nv_bfloat16 h0 = __float2bfloat16(v.x);
    __nv_bfloat16 h1 = __float2bfloat16(v.y);
    __nv_bfloat16 h2 = __float2bfloat16(v.z);
    __nv_bfloat16 h3 = __float2bfloat16(v.w);
    __nv_bfloat16 l0 = __float2bfloat16(v.x - __bfloat162float(h0));
    __nv_bfloat16 l1 = __float2bfloat16(v.y - __bfloat162float(h1));
    __nv_bfloat16 l2 = __float2bfloat16(v.z - __bfloat162float(h2));
    __nv_bfloat16 l3 = __float2bfloat16(v.w - __bfloat162float(h3));
    ((__nv_bfloat162*)hi)[2 * i + 0] = __halves2bfloat162(h0, h1);
    ((__nv_bfloat162*)hi)[2 * i + 1] = __halves2bfloat162(h2, h3);
    ((__nv_bfloat162*)lo)[2 * i + 0] = __halves2bfloat162(l0, l1);
    ((__nv_bfloat162*)lo)[2 * i + 1] = __halves2bfloat162(l2, l3);
}

// ---------------- split-bf16 HMMA GEMM --------------------------------------
// C[8192,1024] = (Ahi+Alo) @ (Whi+Wlo)^T + bias  via 3 passes expressed as
// a 96-chunk K-extension: chunks 0-31 (Ah,Wh), 32-63 (Al,Wh), 64-95 (Ah,Wl).
// EPI: 0 none, 1 phi(x)=x>0?x+1:exp(x)
template<int EPI> __device__ __forceinline__ float epi_f(float x) {
    if (EPI == 1) return x > 0.f ? x + 1.f : expf(x);
    if (EPI == 2) return 1.f / (1.f + expf(-x));
    return x;
}

#define ROWB   80            // padded smem row stride (32 halves + 16B pad)
#define STAGEB (128 * ROWB)  // bytes per A-or-B half-stage (10240)
#define NSTAGE 3
#define KTOT   96

template<int EPI>
__global__ __launch_bounds__(256, 2)
void gemm_mma(const __nv_bfloat16* __restrict__ Ah, const __nv_bfloat16* __restrict__ Al,
              const __nv_bfloat16* __restrict__ Wh, const __nv_bfloat16* __restrict__ Wl,
              const float* __restrict__ bias, float* __restrict__ C)
{
    extern __shared__ char smem[];
    const uint32_t sb = smem_u32(smem);
    const int tid  = threadIdx.x;
    const int lane = tid & 31;
    const int warp = tid >> 5;
    const int wm   = warp >> 2;        // 0-1
    const int wn   = warp & 3;         // 0-3
    const int m0   = blockIdx.y * 128;
    const int n0   = blockIdx.x * 128;

    auto load_stage = [&](int kc, int st) {
        const int ph = kc >> 5;
        const __nv_bfloat16* As = (ph == 1) ? Al : Ah;
        const __nv_bfloat16* Ws = (ph == 2) ? Wl : Wh;
        const int k0 = (kc & 31) * 32;
        const uint32_t sA = sb + st * (2 * STAGEB);
        const uint32_t sB = sA + STAGEB;
#pragma unroll
        for (int i = 0; i < 2; i++) {
            const int idx = tid + i * 256;         // 0..511
            const int row = idx >> 2, c = idx & 3;
            cp16(sA + row * ROWB + c * 16, As + (size_t)(m0 + row) * HDIM + k0 + c * 8);
        }
#pragma unroll
        for (int i = 0; i < 2; i++) {
            const int idx = tid + i * 256;
            const int row = idx >> 2, c = idx & 3;
            cp16(sB + row * ROWB + c * 16, Ws + (size_t)(n0 + row) * HDIM + k0 + c * 8);
        }
        cp_commit();
    };

    float acc[4][4][4];
#pragma unroll
    for (int i = 0; i < 4; i++)
#pragma unroll
        for (int j = 0; j < 4; j++)
#pragma unroll
            for (int k = 0; k < 4; k++) acc[i][j][k] = 0.f;

    load_stage(0, 0);
    load_stage(1, 1);

    for (int kc = 0; kc < KTOT; kc++) {
        cp_wait<1>();
        __syncthreads();
        if (kc + 2 < KTOT) load_stage(kc + 2, (kc + 2) % NSTAGE);
        else               cp_commit();           // keep group counting uniform

        const uint32_t sA = sb + (kc % NSTAGE) * (2 * STAGEB);
        const uint32_t sB = sA + STAGEB;
        const uint32_t lrow = lane & 15;
        const uint32_t lcol = (lane >> 4) * 16;

#pragma unroll
        for (int ks = 0; ks < 2; ks++) {
            uint32_t a[4][4], b[4][2];
#pragma unroll
            for (int mi = 0; mi < 4; mi++) {
                const uint32_t addr = sA + (wm * 64 + mi * 16 + lrow) * ROWB + ks * 32 + lcol;
                ldsm_x4(a[mi][0], a[mi][1], a[mi][2], a[mi][3], addr);
            }
#pragma unroll
            for (int wq = 0; wq < 2; wq++) {
                uint32_t r0, r1, r2, r3;
                const uint32_t addr = sB + (wn * 32 + wq * 16 + lrow) * ROWB + ks * 32 + lcol;
                ldsm_x4(r0, r1, r2, r3, addr);
                b[2 * wq + 0][0] = r0; b[2 * wq + 0][1] = r2;
                b[2 * wq + 1][0] = r1; b[2 * wq + 1][1] = r3;
            }
#pragma unroll
            for (int mi = 0; mi < 4; mi++)
#pragma unroll
                for (int ni = 0; ni < 4; ni++)
                    mma_bf16(acc[mi][ni], a[mi], b[ni]);
        }
    }

    // epilogue
#pragma unroll
    for (int mi = 0; mi < 4; mi++) {
#pragma unroll
        for (int ni = 0; ni < 4; ni++) {
            const int r = m0 + wm * 64 + mi * 16 + (lane >> 2);
            const int c = n0 + wn * 32 + ni * 8 + (lane & 3) * 2;
            const float bx = bias[c], by = bias[c + 1];
            float2 o0, o1;
            o0.x = epi_f<EPI>(acc[mi][ni][0] + bx);
            o0.y = epi_f<EPI>(acc[mi][ni][1] + by);
            o1.x = epi_f<EPI>(acc[mi][ni][2] + bx);
            o1.y = epi_f<EPI>(acc[mi][ni][3] + by);
            *(float2*)(C + (size_t)r * HDIM + c)       = o0;
            *(float2*)(C + (size_t)(r + 8) * HDIM + c) = o1;
        }
    }
}

// ---------------- beta projection: sigmoid(A @ Wb^T + bb), N=16 -------------
#define BROWS  64
#define BSTA   (BROWS * ROWB)        // A half-stage bytes (5120)
#define BSTB   (16 * ROWB)           // W half-stage bytes (1280)
#define BSTAGE (BSTA + BSTB)

__global__ __launch_bounds__(128, 4)
void beta_mma(const __nv_bfloat16* __restrict__ Ah, const __nv_bfloat16* __restrict__ Al,
              const __nv_bfloat16* __restrict__ Wh, const __nv_bfloat16* __restrict__ Wl,
              const float* __restrict__ bb, float* __restrict__ Bout)
{
    extern __shared__ char smem[];
    const uint32_t sb = smem_u32(smem);
    const int tid  = threadIdx.x;
    const int lane = tid & 31;
    const int warp = tid >> 5;         // 0-3, warp handles rows warp*16..+16
    const int m0   = blockIdx.x * BROWS;

    auto load_stage = [&](int kc, int st) {
        const int ph = kc >> 5;
        const __nv_bfloat16* As = (ph == 1) ? Al : Ah;
        const __nv_bfloat16* Ws = (ph == 2) ? Wl : Wh;
        const int k0 = (kc & 31) * 32;
        const uint32_t sA = sb + st * BSTAGE;
        const uint32_t sB = sA + BSTA;
#pragma unroll
        for (int i = 0; i < 2; i++) {
            const int idx = tid + i * 128;        // 0..255
            const int row = idx >> 2, c = idx & 3;
            cp16(sA + row * ROWB + c * 16, As + (size_t)(m0 + row) * HDIM + k0 + c * 8);
        }
        if (tid < 64) {
            const int row = tid >> 2, c = tid & 3;
            cp16(sB + row * ROWB + c * 16, Ws + (size_t)row * HDIM + k0 + c * 8);
        }
        cp_commit();
    };

    float acc[2][4];
#pragma unroll
    for (int i = 0; i < 2; i++)
#pragma unroll
        for (int k = 0; k < 4; k++) acc[i][k] = 0.f;

    load_stage(0, 0);
    load_stage(1, 1);

    for (int kc = 0; kc < KTOT; kc++) {
        cp_wait<1>();
        __syncthreads();
        if (kc + 2 < KTOT) load_stage(kc + 2, (kc + 2) % NSTAGE);
        else               cp_commit();

        const uint32_t sA = sb + (kc % NSTAGE) * BSTAGE;
        const uint32_t sB = sA + BSTA;
        const uint32_t lrow = lane & 15;
        const uint32_t lcol = (lane >> 4) * 16;

#pragma unroll
        for (int ks = 0; ks < 2; ks++) {
            uint32_t a[4], b[2][2];
            ldsm_x4(a[0], a[1], a[2], a[3],
                    sA + (warp * 16 + lrow) * ROWB + ks * 32 + lcol);
            uint32_t r0, r1, r2, r3;
            ldsm_x4(r0, r1, r2, r3, sB + lrow * ROWB + ks * 32 + lcol);
            b[0][0] = r0; b[0][1] = r2;
            b[1][0] = r1; b[1][1] = r3;
            mma_bf16(acc[0], a, b[0]);
            mma_bf16(acc[1], a, b[1]);
        }
    }

#pragma unroll
    for (int ni = 0; ni < 2; ni++) {
        const int r = m0 + warp * 16 + (lane >> 2);
        const int c = ni * 8 + (lane & 3) * 2;
        const float bx = bb[c], by = bb[c + 1];
        float2 o0, o1;
        o0.x = 1.f / (1.f + expf(-(acc[ni][0] + bx)));
        o0.y = 1.f / (1.f + expf(-(acc[ni][1] + by)));
        o1.x = 1.f / (1.f + expf(-(acc[ni][2] + bx)));
        o1.y = 1.f / (1.f + expf(-(acc[ni][3] + by)));
        *(float2*)(Bout + (size_t)r * NHEADS + c)       = o0;
        *(float2*)(Bout + (size_t)(r + 8) * NHEADS + c) = o1;
    }
}

// ---------------- delta-rule diagonal scan: s <- a*s + c --------------------
// a = 1 - b*pk^2 ; c = b*v*pk ; y = s*pq. Emits split-bf16 y directly.
__global__ __launch_bounds__(64)
void scan_kernel(const float* __restrict__ Pq, const float* __restrict__ Pk,
                 const float* __restrict__ Vb, const float* __restrict__ Bs,
                 __nv_bfloat16* __restrict__ Yhi, __nv_bfloat16* __restrict__ Ylo)
{
    const int bh = blockIdx.x;
    const int d  = threadIdx.x;
    const size_t base = (size_t)(bh >> 4) * SEQ * HDIM + (size_t)(bh & 15) * 64 + d;
    const float* pk = Pk + base;
    const float* pq = Pq + base;
    const float* vv = Vb + base;
    __nv_bfloat16* yh = Yhi + base;
    __nv_bfloat16* yl = Ylo + base;
    const float* bp = Bs + (size_t)(bh >> 4) * SEQ * NHEADS + (bh & 15);

    float rpk[16], rpq[16], rv[16], rb[16];
#pragma unroll
    for (int j = 0; j < 16; j++) {
        const size_t o = (size_t)j * HDIM;
        rpk[j] = pk[o]; rpq[j] = pq[o]; rv[j] = vv[o];
        rb[j]  = bp[(size_t)j * NHEADS];
    }

    float s = 0.f;
    for (int t0 = 0; t0 < SEQ; t0 += 16) {
#pragma unroll
        for (int j = 0; j < 16; j++) {
            const int t = t0 + j;
            const float a = 1.f - rb[j] * rpk[j] * rpk[j];
            const float c = rb[j] * rv[j] * rpk[j];
            const float q = rpq[j];
            const int tn = t + 16;
            if (tn < SEQ) {
                const size_t o = (size_t)tn * HDIM;
                rpk[j] = pk[o]; rpq[j] = pq[o]; rv[j] = vv[o];
                rb[j]  = bp[(size_t)tn * NHEADS];
            }
            s = fmaf(a, s, c);
            const float y = s * q;
            const __nv_bfloat16 h = __float2bfloat16(y);
            yh[(size_t)t * HDIM] = h;
            yl[(size_t)t * HDIM] = __float2bfloat16(y - __bfloat162float(h));
        }
    }
}

// ---------------- launch -----------------------------------------------------
extern "C" void kernel_launch(void* const* d_in, const int* in_sizes, int n_in,
                              void* d_out, int out_size)
{
    const float* query = (const float*)d_in[0];
    const float* key   = (const float*)d_in[1];
    const float* value = (const float*)d_in[2];
    const float* beta  = (const float*)d_in[3];
    const float* Wq    = (const float*)d_in[4];
    const float* bq    = (const float*)d_in[5];
    const float* Wk    = (const float*)d_in[6];
    const float* bk    = (const float*)d_in[7];
    const float* Wv    = (const float*)d_in[8];
    const float* bv    = (const float*)d_in[9];
    const float* Wb    = (const float*)d_in[10];
    const float* bb    = (const float*)d_in[11];
    const float* Wo    = (const float*)d_in[12];
    const float* bo    = (const float*)d_in[13];
    float* out = (float*)d_out;

    __nv_bfloat16 *pAhi, *pAlo, *pWqh, *pWql, *pWkh, *pWkl, *pWvh, *pWvl, *pWoh, *pWol, *pWbh, *pWbl;
    float *pPq, *pPk, *pV, *pB;
    cudaGetSymbolAddress((void**)&pAhi, g_Ahi);
    cudaGetSymbolAddress((void**)&pAlo, g_Alo);
    cudaGetSymbolAddress((void**)&pWqh, g_Wqhi);
    cudaGetSymbolAddress((void**)&pWql, g_Wqlo);
    cudaGetSymbolAddress((void**)&pWkh, g_Wkhi);
    cudaGetSymbolAddress((void**)&pWkl, g_Wklo);
    cudaGetSymbolAddress((void**)&pWvh, g_Wvhi);
    cudaGetSymbolAddress((void**)&pWvl, g_Wvlo);
    cudaGetSymbolAddress((void**)&pWoh, g_Wohi);
    cudaGetSymbolAddress((void**)&pWol, g_Wolo);
    cudaGetSymbolAddress((void**)&pWbh, g_Wbhi);
    cudaGetSymbolAddress((void**)&pWbl, g_Wblo);
    cudaGetSymbolAddress((void**)&pPq, g_Pq);
    cudaGetSymbolAddress((void**)&pPk, g_Pk);
    cudaGetSymbolAddress((void**)&pV,  g_V);
    cudaGetSymbolAddress((void**)&pB,  g_B);

    const int SMEM_GEMM = NSTAGE * 2 * STAGEB;   // 61440
    const int SMEM_BETA = NSTAGE * BSTAGE;       // 19200
    cudaFuncSetAttribute(gemm_mma<0>, cudaFuncAttributeMaxDynamicSharedMemorySize, SMEM_GEMM);
    cudaFuncSetAttribute(gemm_mma<1>, cudaFuncAttributeMaxDynamicSharedMemorySize, SMEM_GEMM);
    cudaFuncSetAttribute(beta_mma,    cudaFuncAttributeMaxDynamicSharedMemorySize, SMEM_BETA);

    const int N4A = MROWS * HDIM / 4;
    const int N4W = HDIM * HDIM / 4;
    const int N4B = NHEADS * HDIM / 4;

    // weight splits
    conv_split<<<N4W / 256, 256>>>(Wq, pWqh, pWql, N4W);
    conv_split<<<N4W / 256, 256>>>(Wk, pWkh, pWkl, N4W);
    conv_split<<<N4W / 256, 256>>>(Wv, pWvh, pWvl, N4W);
    conv_split<<<N4W / 256, 256>>>(Wo, pWoh, pWol, N4W);
    conv_split<<<N4B / 256, 256>>>(Wb, pWbh, pWbl, N4B);

    const dim3 gBig(8, 64), blk(256);

    // q projection + phi
    conv_split<<<N4A / 256, 256>>>(query, pAhi, pAlo, N4A);
    gemm_mma<1><<<gBig, blk, SMEM_GEMM>>>(pAhi, pAlo, pWqh, pWql, bq, pPq);
    // k projection + phi
    conv_split<<<N4A / 256, 256>>>(key, pAhi, pAlo, N4A);
    gemm_mma<1><<<gBig, blk, SMEM_GEMM>>>(pAhi, pAlo, pWkh, pWkl, bk, pPk);
    // v projection
    conv_split<<<N4A / 256, 256>>>(value, pAhi, pAlo, N4A);
    gemm_mma<0><<<gBig, blk, SMEM_GEMM>>>(pAhi, pAlo, pWvh, pWvl, bv, pV);
    // beta projection + sigmoid
    conv_split<<<N4A / 256, 256>>>(beta, pAhi, pAlo, N4A);
    beta_mma<<<MROWS / BROWS, 128, SMEM_BETA>>>(pAhi, pAlo, pWbh, pWbl, bb, pB);
    // scan (emits split-bf16 Y directly into the GEMM input buffers)
    scan_kernel<<<BATCH * NHEADS, 64>>>(pPq, pPk, pV, pB, pAhi, pAlo);
    // output projection
    gemm_mma<0><<<gBig, blk, SMEM_GEMM>>>(pAhi, pAlo, pWoh, pWol, bo, out);
}

// round 7
// speedup vs baseline: 2.2379x; 1.0790x over previous
#include <cuda_runtime.h>
#include <cuda_bf16.h>
#include <math.h>
#include <stdint.h>

#define BATCH   4
#define SEQ     2048
#define HDIM    1024
#define NHEADS  16
#define MROWS   8192

// ---------------- scratch (device globals; no runtime allocation) -----------
__device__ __nv_bfloat16 g_Ahi[(size_t)MROWS * HDIM];
__device__ __nv_bfloat16 g_Alo[(size_t)MROWS * HDIM];
__device__ __nv_bfloat16 g_Wqhi[(size_t)HDIM * HDIM];
__device__ __nv_bfloat16 g_Wqlo[(size_t)HDIM * HDIM];
__device__ __nv_bfloat16 g_Wkhi[(size_t)HDIM * HDIM];
__device__ __nv_bfloat16 g_Wklo[(size_t)HDIM * HDIM];
__device__ __nv_bfloat16 g_Wvhi[(size_t)HDIM * HDIM];
__device__ __nv_bfloat16 g_Wvlo[(size_t)HDIM * HDIM];
__device__ __nv_bfloat16 g_Wohi[(size_t)HDIM * HDIM];
__device__ __nv_bfloat16 g_Wolo[(size_t)HDIM * HDIM];
__device__ __nv_bfloat16 g_Wbhi[(size_t)NHEADS * HDIM];
__device__ __nv_bfloat16 g_Wblo[(size_t)NHEADS * HDIM];
__device__ float g_Pq[(size_t)MROWS * HDIM];
__device__ float g_Pk[(size_t)MROWS * HDIM];
__device__ float g_V [(size_t)MROWS * HDIM];
__device__ float g_B [(size_t)MROWS * NHEADS];

// ---------------- baseline-PTX helpers --------------------------------------
__device__ __forceinline__ uint32_t smem_u32(const void* p) {
    uint32_t a;
    asm("{ .reg .u64 t; cvta.to.shared.u64 t, %1; cvt.u32.u64 %0, t; }" : "=r"(a) : "l"(p));
    return a;
}
__device__ __forceinline__ void cp16(uint32_t dst, const void* src) {
    asm volatile("cp.async.cg.shared.global [%0], [%1], 16;\n" :: "r"(dst), "l"(src) : "memory");
}
__device__ __forceinline__ void cp_commit() {
    asm volatile("cp.async.commit_group;\n" ::: "memory");
}
template<int N> __device__ __forceinline__ void cp_wait() {
    asm volatile("cp.async.wait_group %0;\n" :: "n"(N) : "memory");
}
__device__ __forceinline__ void ldsm_x4(uint32_t& r0, uint32_t& r1, uint32_t& r2, uint32_t& r3,
                                        uint32_t addr) {
    asm volatile("ldmatrix.sync.aligned.m8n8.x4.shared.b16 {%0,%1,%2,%3}, [%4];"
                 : "=r"(r0), "=r"(r1), "=r"(r2), "=r"(r3) : "r"(addr));
}
__device__ __forceinline__ void mma_bf16(float* c, const uint32_t* a, const uint32_t* b) {
    asm volatile(
        "mma.sync.aligned.m16n8k16.row.col.f32.bf16.bf16.f32 "
        "{%0,%1,%2,%3}, {%4,%5,%6,%7}, {%8,%9}, {%0,%1,%2,%3};"
        : "+f"(c[0]), "+f"(c[1]), "+f"(c[2]), "+f"(c[3])
        : "r"(a[0]), "r"(a[1]), "r"(a[2]), "r"(a[3]), "r"(b[0]), "r"(b[1]));
}

// ---------------- split conversion: fp32 -> bf16 hi + bf16 lo ---------------
__global__ __launch_bounds__(256)
void conv_split(const float* __restrict__ x, __nv_bfloat16* __restrict__ hi,
                __nv_bfloat16* __restrict__ lo, int n4)
{
    int i = blockIdx.x * blockDim.x + threadIdx.x;
    if (i >= n4) return;
    float4 v = ((const float4*)x)[i];
    __nv_bfloat16 h0 = __float2bfloat16(v.x);
    __nv_bfloat16 h1 = __float2bfloat16(v.y);
    __nv_bfloat16 h2 = __float2bfloat16(v.z);
    __nv_bfloat16 h3 = __float2bfloat16(v.w);
    __nv_bfloat16 l0 = __float2bfloat16(v.x - __bfloat162float(h0));
    __nv_bfloat16 l1 = __float2bfloat16(v.y - __bfloat162float(h1));
    __nv_bfloat16 l2 = __float2bfloat16(v.z - __bfloat162float(h2));
    __nv_bfloat16 l3 = __float2bfloat16(v.w - __bfloat162float(h3));
    ((__nv_bfloat162*)hi)[2 * i + 0] = __halves2bfloat162(h0, h1);
    ((__nv_bfloat162*)hi)[2 * i + 1] = __halves2bfloat162(h2, h3);
    ((__nv_bfloat162*)lo)[2 * i + 0] = __halves2bfloat162(l0, l1);
    ((__nv_bfloat162*)lo)[2 * i + 1] = __halves2bfloat162(l2, l3);
}

// ---------------- split-bf16 HMMA GEMM (single-pass, 4-plane chunks) --------
// C[8192,1024] = (Ahi+Alo) @ (Whi+Wlo)^T + bias.
// Tile 128x256, 8 warps (2x4 grid, 64x64 warp tiles). Each K=32 chunk loads
// Ah,Al,Wh,Wl once and issues 3 MMA combos: AhWh + AlWh + AhWl.
template<int EPI> __device__ __forceinline__ float epi_f(float x) {
    if (EPI == 1) return x > 0.f ? x + 1.f : expf(x);
    if (EPI == 2) return 1.f / (1.f + expf(-x));
    return x;
}

#define ROWB    80                  // smem row stride: 64B data + 16B pad
#define A_PL    (128 * ROWB)        // 10240 bytes per A plane
#define B_PL    (256 * ROWB)        // 20480 bytes per B plane
#define STAGEB  (2 * A_PL + 2 * B_PL)  // 61440
#define NSTAGE  3
#define KCH     32

template<int EPI>
__global__ __launch_bounds__(256)
void gemm_mma(const __nv_bfloat16* __restrict__ Ah, const __nv_bfloat16* __restrict__ Al,
              const __nv_bfloat16* __restrict__ Wh, const __nv_bfloat16* __restrict__ Wl,
              const float* __restrict__ bias, float* __restrict__ C)
{
    extern __shared__ char smem[];
    const uint32_t sb = smem_u32(smem);
    const int tid  = threadIdx.x;
    const int lane = tid & 31;
    const int warp = tid >> 5;
    const int wm   = warp >> 2;        // 0-1  (64-row slab)
    const int wn   = warp & 3;         // 0-3  (64-col slab)
    const int m0   = blockIdx.y * 128;
    const int n0   = blockIdx.x * 256;

    auto load_stage = [&](int kc, int st) {
        const int k0 = kc * 32;
        const uint32_t sA = sb + st * STAGEB;
        const uint32_t sB = sA + 2 * A_PL;
        // A: 2 planes x 128 rows x 4 x 16B  (1024 cp16)
#pragma unroll
        for (int i = 0; i < 4; i++) {
            const int idx = tid + i * 256;
            const int pl  = idx >> 9;
            const int r   = (idx >> 2) & 127;
            const int c   = idx & 3;
            cp16(sA + pl * A_PL + r * ROWB + c * 16,
                 (pl ? Al : Ah) + (size_t)(m0 + r) * HDIM + k0 + c * 8);
        }
        // B: 2 planes x 256 rows x 4 x 16B  (2048 cp16)
#pragma unroll
        for (int i = 0; i < 8; i++) {
            const int idx = tid + i * 256;
            const int pl  = idx >> 10;
            const int r   = (idx >> 2) & 255;
            const int c   = idx & 3;
            cp16(sB + pl * B_PL + r * ROWB + c * 16,
                 (pl ? Wl : Wh) + (size_t)(n0 + r) * HDIM + k0 + c * 8);
        }
        cp_commit();
    };

    float acc[4][8][4];
#pragma unroll
    for (int i = 0; i < 4; i++)
#pragma unroll
        for (int j = 0; j < 8; j++)
#pragma unroll
            for (int k = 0; k < 4; k++) acc[i][j][k] = 0.f;

    load_stage(0, 0);
    load_stage(1, 1);

    const uint32_t lrow = lane & 15;
    const uint32_t lcol = (lane >> 4) * 16;

    for (int kc = 0; kc < KCH; kc++) {
        if (kc > 0) __syncthreads();               // stage (kc+2)%3 free to overwrite
        if (kc + 2 < KCH) load_stage(kc + 2, (kc + 2) % NSTAGE);
        else              cp_commit();             // keep group counting uniform
        cp_wait<2>();                              // chunk kc resident
        __syncthreads();

        const uint32_t sA = sb + (kc % NSTAGE) * STAGEB;
        const uint32_t sB = sA + 2 * A_PL;

#pragma unroll
        for (int ks = 0; ks < 2; ks++) {
            uint32_t aH[4][4], aL[4][4], b[8][2];
#pragma unroll
            for (int mi = 0; mi < 4; mi++) {
                const uint32_t ra = (wm * 64 + mi * 16 + lrow) * ROWB + ks * 32 + lcol;
                ldsm_x4(aH[mi][0], aH[mi][1], aH[mi][2], aH[mi][3], sA + ra);
                ldsm_x4(aL[mi][0], aL[mi][1], aL[mi][2], aL[mi][3], sA + A_PL + ra);
            }
            // Wh plane: AhWh + AlWh
#pragma unroll
            for (int bq = 0; bq < 4; bq++) {
                uint32_t r0, r1, r2, r3;
                ldsm_x4(r0, r1, r2, r3,
                        sB + (wn * 64 + bq * 16 + lrow) * ROWB + ks * 32 + lcol);
                b[2 * bq + 0][0] = r0; b[2 * bq + 0][1] = r2;
                b[2 * bq + 1][0] = r1; b[2 * bq + 1][1] = r3;
            }
#pragma unroll
            for (int mi = 0; mi < 4; mi++)
#pragma unroll
                for (int ni = 0; ni < 8; ni++) {
                    mma_bf16(acc[mi][ni], aH[mi], b[ni]);
                    mma_bf16(acc[mi][ni], aL[mi], b[ni]);
                }
            // Wl plane: AhWl
#pragma unroll
            for (int bq = 0; bq < 4; bq++) {
                uint32_t r0, r1, r2, r3;
                ldsm_x4(r0, r1, r2, r3,
                        sB + B_PL + (wn * 64 + bq * 16 + lrow) * ROWB + ks * 32 + lcol);
                b[2 * bq + 0][0] = r0; b[2 * bq + 0][1] = r2;
                b[2 * bq + 1][0] = r1; b[2 * bq + 1][1] = r3;
            }
#pragma unroll
            for (int mi = 0; mi < 4; mi++)
#pragma unroll
                for (int ni = 0; ni < 8; ni++)
                    mma_bf16(acc[mi][ni], aH[mi], b[ni]);
        }
    }

    // epilogue
#pragma unroll
    for (int mi = 0; mi < 4; mi++) {
#pragma unroll
        for (int ni = 0; ni < 8; ni++) {
            const int r = m0 + wm * 64 + mi * 16 + (lane >> 2);
            const int c = n0 + wn * 64 + ni * 8 + (lane & 3) * 2;
            const float bx = bias[c], by = bias[c + 1];
            float2 o0, o1;
            o0.x = epi_f<EPI>(acc[mi][ni][0] + bx);
            o0.y = epi_f<EPI>(acc[mi][ni][1] + by);
            o1.x = epi_f<EPI>(acc[mi][ni][2] + bx);
            o1.y = epi_f<EPI>(acc[mi][ni][3] + by);
            *(float2*)(C + (size_t)r * HDIM + c)       = o0;
            *(float2*)(C + (size_t)(r + 8) * HDIM + c) = o1;
        }
    }
}

// ---------------- beta projection: sigmoid(A @ Wb^T + bb), N=16 -------------
#define BROWS  64
#define BSTA   (BROWS * ROWB)        // 5120
#define BSTB   (16 * ROWB)           // 1280
#define BSTAGE (BSTA + BSTB)
#define BKTOT  96

__global__ __launch_bounds__(128, 4)
void beta_mma(const __nv_bfloat16* __restrict__ Ah, const __nv_bfloat16* __restrict__ Al,
              const __nv_bfloat16* __restrict__ Wh, const __nv_bfloat16* __restrict__ Wl,
              const float* __restrict__ bb, float* __restrict__ Bout)
{
    extern __shared__ char smem[];
    const uint32_t sb = smem_u32(smem);
    const int tid  = threadIdx.x;
    const int lane = tid & 31;
    const int warp = tid >> 5;
    const int m0   = blockIdx.x * BROWS;

    auto load_stage = [&](int kc, int st) {
        const int ph = kc >> 5;
        const __nv_bfloat16* As = (ph == 1) ? Al : Ah;
        const __nv_bfloat16* Ws = (ph == 2) ? Wl : Wh;
        const int k0 = (kc & 31) * 32;
        const uint32_t sA = sb + st * BSTAGE;
        const uint32_t sB = sA + BSTA;
#pragma unroll
        for (int i = 0; i < 2; i++) {
            const int idx = tid + i * 128;
            const int row = idx >> 2, c = idx & 3;
            cp16(sA + row * ROWB + c * 16, As + (size_t)(m0 + row) * HDIM + k0 + c * 8);
        }
        if (tid < 64) {
            const int row = tid >> 2, c = tid & 3;
            cp16(sB + row * ROWB + c * 16, Ws + (size_t)row * HDIM + k0 + c * 8);
        }
        cp_commit();
    };

    float acc[2][4];
#pragma unroll
    for (int i = 0; i < 2; i++)
#pragma unroll
        for (int k = 0; k < 4; k++) acc[i][k] = 0.f;

    load_stage(0, 0);
    load_stage(1, 1);

    for (int kc = 0; kc < BKTOT; kc++) {
        cp_wait<1>();
        __syncthreads();
        if (kc + 2 < BKTOT) load_stage(kc + 2, (kc + 2) % NSTAGE);
        else                cp_commit();

        const uint32_t sA = sb + (kc % NSTAGE) * BSTAGE;
        const uint32_t sB = sA + BSTA;
        const uint32_t lrow = lane & 15;
        const uint32_t lcol = (lane >> 4) * 16;

#pragma unroll
        for (int ks = 0; ks < 2; ks++) {
            uint32_t a[4], b[2][2];
            ldsm_x4(a[0], a[1], a[2], a[3],
                    sA + (warp * 16 + lrow) * ROWB + ks * 32 + lcol);
            uint32_t r0, r1, r2, r3;
            ldsm_x4(r0, r1, r2, r3, sB + lrow * ROWB + ks * 32 + lcol);
            b[0][0] = r0; b[0][1] = r2;
            b[1][0] = r1; b[1][1] = r3;
            mma_bf16(acc[0], a, b[0]);
            mma_bf16(acc[1], a, b[1]);
        }
    }

#pragma unroll
    for (int ni = 0; ni < 2; ni++) {
        const int r = m0 + warp * 16 + (lane >> 2);
        const int c = ni * 8 + (lane & 3) * 2;
        const float bx = bb[c], by = bb[c + 1];
        float2 o0, o1;
        o0.x = 1.f / (1.f + expf(-(acc[ni][0] + bx)));
        o0.y = 1.f / (1.f + expf(-(acc[ni][1] + by)));
        o1.x = 1.f / (1.f + expf(-(acc[ni][2] + bx)));
        o1.y = 1.f / (1.f + expf(-(acc[ni][3] + by)));
        *(float2*)(Bout + (size_t)r * NHEADS + c)       = o0;
        *(float2*)(Bout + (size_t)(r + 8) * NHEADS + c) = o1;
    }
}

// ---------------- delta-rule diagonal scan: s <- a*s + c --------------------
__global__ __launch_bounds__(64)
void scan_kernel(const float* __restrict__ Pq, const float* __restrict__ Pk,
                 const float* __restrict__ Vb, const float* __restrict__ Bs,
                 __nv_bfloat16* __restrict__ Yhi, __nv_bfloat16* __restrict__ Ylo)
{
    const int bh = blockIdx.x;
    const int d  = threadIdx.x;
    const size_t base = (size_t)(bh >> 4) * SEQ * HDIM + (size_t)(bh & 15) * 64 + d;
    const float* pk = Pk + base;
    const float* pq = Pq + base;
    const float* vv = Vb + base;
    __nv_bfloat16* yh = Yhi + base;
    __nv_bfloat16* yl = Ylo + base;
    const float* bp = Bs + (size_t)(bh >> 4) * SEQ * NHEADS + (bh & 15);

    float rpk[16], rpq[16], rv[16], rb[16];
#pragma unroll
    for (int j = 0; j < 16; j++) {
        const size_t o = (size_t)j * HDIM;
        rpk[j] = pk[o]; rpq[j] = pq[o]; rv[j] = vv[o];
        rb[j]  = bp[(size_t)j * NHEADS];
    }

    float s = 0.f;
    for (int t0 = 0; t0 < SEQ; t0 += 16) {
#pragma unroll
        for (int j = 0; j < 16; j++) {
            const int t = t0 + j;
            const float a = 1.f - rb[j] * rpk[j] * rpk[j];
            const float c = rb[j] * rv[j] * rpk[j];
            const float q = rpq[j];
            const int tn = t + 16;
            if (tn < SEQ) {
                const size_t o = (size_t)tn * HDIM;
                rpk[j] = pk[o]; rpq[j] = pq[o]; rv[j] = vv[o];
                rb[j]  = bp[(size_t)tn * NHEADS];
            }
            s = fmaf(a, s, c);
            const float y = s * q;
            const __nv_bfloat16 h = __float2bfloat16(y);
            yh[(size_t)t * HDIM] = h;
            yl[(size_t)t * HDIM] = __float2bfloat16(y - __bfloat162float(h));
        }
    }
}

// ---------------- launch -----------------------------------------------------
extern "C" void kernel_launch(void* const* d_in, const int* in_sizes, int n_in,
                              void* d_out, int out_size)
{
    const float* query = (const float*)d_in[0];
    const float* key   = (const float*)d_in[1];
    const float* value = (const float*)d_in[2];
    const float* beta  = (const float*)d_in[3];
    const float* Wq    = (const float*)d_in[4];
    const float* bq    = (const float*)d_in[5];
    const float* Wk    = (const float*)d_in[6];
    const float* bk    = (const float*)d_in[7];
    const float* Wv    = (const float*)d_in[8];
    const float* bv    = (const float*)d_in[9];
    const float* Wb    = (const float*)d_in[10];
    const float* bb    = (const float*)d_in[11];
    const float* Wo    = (const float*)d_in[12];
    const float* bo    = (const float*)d_in[13];
    float* out = (float*)d_out;

    __nv_bfloat16 *pAhi, *pAlo, *pWqh, *pWql, *pWkh, *pWkl, *pWvh, *pWvl, *pWoh, *pWol, *pWbh, *pWbl;
    float *pPq, *pPk, *pV, *pB;
    cudaGetSymbolAddress((void**)&pAhi, g_Ahi);
    cudaGetSymbolAddress((void**)&pAlo, g_Alo);
    cudaGetSymbolAddress((void**)&pWqh, g_Wqhi);
    cudaGetSymbolAddress((void**)&pWql, g_Wqlo);
    cudaGetSymbolAddress((void**)&pWkh, g_Wkhi);
    cudaGetSymbolAddress((void**)&pWkl, g_Wklo);
    cudaGetSymbolAddress((void**)&pWvh, g_Wvhi);
    cudaGetSymbolAddress((void**)&pWvl, g_Wvlo);
    cudaGetSymbolAddress((void**)&pWoh, g_Wohi);
    cudaGetSymbolAddress((void**)&pWol, g_Wolo);
    cudaGetSymbolAddress((void**)&pWbh, g_Wbhi);
    cudaGetSymbolAddress((void**)&pWbl, g_Wblo);
    cudaGetSymbolAddress((void**)&pPq, g_Pq);
    cudaGetSymbolAddress((void**)&pPk, g_Pk);
    cudaGetSymbolAddress((void**)&pV,  g_V);
    cudaGetSymbolAddress((void**)&pB,  g_B);

    const int SMEM_GEMM = NSTAGE * STAGEB;       // 184320
    const int SMEM_BETA = NSTAGE * BSTAGE;       // 19200
    cudaFuncSetAttribute(gemm_mma<0>, cudaFuncAttributeMaxDynamicSharedMemorySize, SMEM_GEMM);
    cudaFuncSetAttribute(gemm_mma<1>, cudaFuncAttributeMaxDynamicSharedMemorySize, SMEM_GEMM);
    cudaFuncSetAttribute(beta_mma,    cudaFuncAttributeMaxDynamicSharedMemorySize, SMEM_BETA);

    const int N4A = MROWS * HDIM / 4;
    const int N4W = HDIM * HDIM / 4;
    const int N4B = NHEADS * HDIM / 4;

    // weight splits
    conv_split<<<N4W / 256, 256>>>(Wq, pWqh, pWql, N4W);
    conv_split<<<N4W / 256, 256>>>(Wk, pWkh, pWkl, N4W);
    conv_split<<<N4W / 256, 256>>>(Wv, pWvh, pWvl, N4W);
    conv_split<<<N4W / 256, 256>>>(Wo, pWoh, pWol, N4W);
    conv_split<<<N4B / 256, 256>>>(Wb, pWbh, pWbl, N4B);

    const dim3 gBig(4, 64), blk(256);

    // q projection + phi
    conv_split<<<N4A / 256, 256>>>(query, pAhi, pAlo, N4A);
    gemm_mma<1><<<gBig, blk, SMEM_GEMM>>>(pAhi, pAlo, pWqh, pWql, bq, pPq);
    // k projection + phi
    conv_split<<<N4A / 256, 256>>>(key, pAhi, pAlo, N4A);
    gemm_mma<1><<<gBig, blk, SMEM_GEMM>>>(pAhi, pAlo, pWkh, pWkl, bk, pPk);
    // v projection
    conv_split<<<N4A / 256, 256>>>(value, pAhi, pAlo, N4A);
    gemm_mma<0><<<gBig, blk, SMEM_GEMM>>>(pAhi, pAlo, pWvh, pWvl, bv, pV);
    // beta projection + sigmoid
    conv_split<<<N4A / 256, 256>>>(beta, pAhi, pAlo, N4A);
    beta_mma<<<MROWS / BROWS, 128, SMEM_BETA>>>(pAhi, pAlo, pWbh, pWbl, bb, pB);
    // scan (emits split-bf16 Y directly into the GEMM input buffers)
    scan_kernel<<<BATCH * NHEADS, 64>>>(pPq, pPk, pV, pB, pAhi, pAlo);
    // output projection
    gemm_mma<0><<<gBig, blk, SMEM_GEMM>>>(pAhi, pAlo, pWoh, pWol, bo, out);
}

// round 12
// speedup vs baseline: 2.4592x; 1.0989x over previous
#include <cuda_runtime.h>
#include <cuda_bf16.h>
#include <math.h>
#include <stdint.h>

#define BATCH   4
#define SEQ     2048
#define HDIM    1024
#define NHEADS  16
#define MROWS   8192

// ---------------- scratch (device globals; no runtime allocation) -----------
__device__ __nv_bfloat16 g_Ahi[(size_t)MROWS * HDIM];
__device__ __nv_bfloat16 g_Alo[(size_t)MROWS * HDIM];
__device__ __nv_bfloat16 g_Wqhi[(size_t)HDIM * HDIM];
__device__ __nv_bfloat16 g_Wqlo[(size_t)HDIM * HDIM];
__device__ __nv_bfloat16 g_Wkhi[(size_t)HDIM * HDIM];
__device__ __nv_bfloat16 g_Wklo[(size_t)HDIM * HDIM];
__device__ __nv_bfloat16 g_Wvhi[(size_t)HDIM * HDIM];
__device__ __nv_bfloat16 g_Wvlo[(size_t)HDIM * HDIM];
__device__ __nv_bfloat16 g_Wohi[(size_t)HDIM * HDIM];
__device__ __nv_bfloat16 g_Wolo[(size_t)HDIM * HDIM];
__device__ __nv_bfloat16 g_Wbhi[(size_t)NHEADS * HDIM];
__device__ __nv_bfloat16 g_Wblo[(size_t)NHEADS * HDIM];
__device__ float g_Pq[(size_t)MROWS * HDIM];
__device__ float g_Pk[(size_t)MROWS * HDIM];
__device__ float g_V [(size_t)MROWS * HDIM];
__device__ float g_B [(size_t)MROWS * NHEADS];

// ---------------- baseline-PTX helpers --------------------------------------
__device__ __forceinline__ uint32_t smem_u32(const void* p) {
    uint32_t a;
    asm("{ .reg .u64 t; cvta.to.shared.u64 t, %1; cvt.u32.u64 %0, t; }" : "=r"(a) : "l"(p));
    return a;
}
__device__ __forceinline__ void cp16(uint32_t dst, const void* src) {
    asm volatile("cp.async.cg.shared.global [%0], [%1], 16;\n" :: "r"(dst), "l"(src) : "memory");
}
__device__ __forceinline__ void cp_commit() {
    asm volatile("cp.async.commit_group;\n" ::: "memory");
}
template<int N> __device__ __forceinline__ void cp_wait() {
    asm volatile("cp.async.wait_group %0;\n" :: "n"(N) : "memory");
}
__device__ __forceinline__ void ldsm_x4(uint32_t& r0, uint32_t& r1, uint32_t& r2, uint32_t& r3,
                                        uint32_t addr) {
    asm volatile("ldmatrix.sync.aligned.m8n8.x4.shared.b16 {%0,%1,%2,%3}, [%4];"
                 : "=r"(r0), "=r"(r1), "=r"(r2), "=r"(r3) : "r"(addr));
}
__device__ __forceinline__ void mma_bf16(float* c, const uint32_t* a, const uint32_t* b) {
    asm volatile(
        "mma.sync.aligned.m16n8k16.row.col.f32.bf16.bf16.f32 "
        "{%0,%1,%2,%3}, {%4,%5,%6,%7}, {%8,%9}, {%0,%1,%2,%3};"
        : "+f"(c[0]), "+f"(c[1]), "+f"(c[2]), "+f"(c[3])
        : "r"(a[0]), "r"(a[1]), "r"(a[2]), "r"(a[3]), "r"(b[0]), "r"(b[1]));
}

// ---------------- split conversion: fp32 -> bf16 hi + bf16 lo ---------------
__global__ __launch_bounds__(256)
void conv_split(const float* __restrict__ x, __nv_bfloat16* __restrict__ hi,
                __nv_bfloat16* __restrict__ lo, int n4)
{
    int i = blockIdx.x * blockDim.x + threadIdx.x;
    if (i >= n4) return;
    float4 v = ((const float4*)x)[i];
    __nv_bfloat16 h0 = __float2bfloat16(v.x);
    __nv_bfloat16 h1 = __float2bfloat16(v.y);
    __nv_bfloat16 h2 = __float2bfloat16(v.z);
    __nv_bfloat16 h3 = __float2bfloat16(v.w);
    __nv_bfloat16 l0 = __float2bfloat16(v.x - __bfloat162float(h0));
    __nv_bfloat16 l1 = __float2bfloat16(v.y - __bfloat162float(h1));
    __nv_bfloat16 l2 = __float2bfloat16(v.z - __bfloat162float(h2));
    __nv_bfloat16 l3 = __float2bfloat16(v.w - __bfloat162float(h3));
    ((__nv_bfloat162*)hi)[2 * i + 0] = __halves2bfloat162(h0, h1);
    ((__nv_bfloat162*)hi)[2 * i + 1] = __halves2bfloat162(h2, h3);
    ((__nv_bfloat162*)lo)[2 * i + 0] = __halves2bfloat162(l0, l1);
    ((__nv_bfloat162*)lo)[2 * i + 1] = __halves2bfloat162(l2, l3);
}

// ---------------- split-bf16 HMMA GEMM (128x128 tile, 2 CTAs/SM) ------------
// C[8192,1024] = (Ahi+Alo) @ (Whi+Wlo)^T + bias. 4-plane single-pass chunks:
// each K=32 chunk loads Ah,Al,Wh,Wl once, issues AhWh + AlWh + AhWl.
template<int EPI> __device__ __forceinline__ float epi_f(float x) {
    if (EPI == 1) return x > 0.f ? x + 1.f : expf(x);
    if (EPI == 2) return 1.f / (1.f + expf(-x));
    return x;
}

#define ROWB    80                  // smem row stride: 64B data + 16B pad
#define A_PL    (128 * ROWB)        // 10240 bytes per plane (A and B both 128 rows)
#define STAGEB  (4 * A_PL)          // 40960
#define KCH     32

template<int EPI>
__global__ __launch_bounds__(256, 2)
void gemm_mma(const __nv_bfloat16* __restrict__ Ah, const __nv_bfloat16* __restrict__ Al,
              const __nv_bfloat16* __restrict__ Wh, const __nv_bfloat16* __restrict__ Wl,
              const float* __restrict__ bias, float* __restrict__ C)
{
    extern __shared__ char smem[];
    const uint32_t sb = smem_u32(smem);
    const int tid  = threadIdx.x;
    const int lane = tid & 31;
    const int warp = tid >> 5;
    const int wm   = warp >> 2;        // 0-1  (64-row slab)
    const int wn   = warp & 3;         // 0-3  (32-col slab)
    const int m0   = blockIdx.y * 128;
    const int n0   = blockIdx.x * 128;

    auto load_stage = [&](int kc, int st) {
        const int k0 = kc * 32;
        const uint32_t sA = sb + st * STAGEB;
        const uint32_t sB = sA + 2 * A_PL;
        // A: 2 planes x 128 rows x 4 x 16B  (1024 cp16)
#pragma unroll
        for (int i = 0; i < 4; i++) {
            const int idx = tid + i * 256;
            const int pl  = idx >> 9;
            const int r   = (idx >> 2) & 127;
            const int c   = idx & 3;
            cp16(sA + pl * A_PL + r * ROWB + c * 16,
                 (pl ? Al : Ah) + (size_t)(m0 + r) * HDIM + k0 + c * 8);
        }
        // B: 2 planes x 128 rows x 4 x 16B  (1024 cp16)
#pragma unroll
        for (int i = 0; i < 4; i++) {
            const int idx = tid + i * 256;
            const int pl  = idx >> 9;
            const int r   = (idx >> 2) & 127;
            const int c   = idx & 3;
            cp16(sB + pl * A_PL + r * ROWB + c * 16,
                 (pl ? Wl : Wh) + (size_t)(n0 + r) * HDIM + k0 + c * 8);
        }
        cp_commit();
    };

    float acc[4][4][4];
#pragma unroll
    for (int i = 0; i < 4; i++)
#pragma unroll
        for (int j = 0; j < 4; j++)
#pragma unroll
            for (int k = 0; k < 4; k++) acc[i][j][k] = 0.f;

    load_stage(0, 0);

    const uint32_t lrow = lane & 15;
    const uint32_t lcol = (lane >> 4) * 16;

    for (int kc = 0; kc < KCH; kc++) {
        if (kc + 1 < KCH) {
            load_stage(kc + 1, (kc + 1) & 1);   // stage safe: guarded by prev-iter sync
            cp_wait<1>();                       // chunk kc resident
        } else {
            cp_wait<0>();
        }
        __syncthreads();

        const uint32_t sA = sb + (kc & 1) * STAGEB;
        const uint32_t sB = sA + 2 * A_PL;

#pragma unroll
        for (int ks = 0; ks < 2; ks++) {
            uint32_t aH[4][4], aL[4][4], b[4][2];
#pragma unroll
            for (int mi = 0; mi < 4; mi++) {
                const uint32_t ra = (wm * 64 + mi * 16 + lrow) * ROWB + ks * 32 + lcol;
                ldsm_x4(aH[mi][0], aH[mi][1], aH[mi][2], aH[mi][3], sA + ra);
                ldsm_x4(aL[mi][0], aL[mi][1], aL[mi][2], aL[mi][3], sA + A_PL + ra);
            }
            // Wh plane: AhWh + AlWh
#pragma unroll
            for (int bq = 0; bq < 2; bq++) {
                uint32_t r0, r1, r2, r3;
                ldsm_x4(r0, r1, r2, r3,
                        sB + (wn * 32 + bq * 16 + lrow) * ROWB + ks * 32 + lcol);
                b[2 * bq + 0][0] = r0; b[2 * bq + 0][1] = r2;
                b[2 * bq + 1][0] = r1; b[2 * bq + 1][1] = r3;
            }
#pragma unroll
            for (int mi = 0; mi < 4; mi++)
#pragma unroll
                for (int ni = 0; ni < 4; ni++) {
                    mma_bf16(acc[mi][ni], aH[mi], b[ni]);
                    mma_bf16(acc[mi][ni], aL[mi], b[ni]);
                }
            // Wl plane: AhWl
#pragma unroll
            for (int bq = 0; bq < 2; bq++) {
                uint32_t r0, r1, r2, r3;
                ldsm_x4(r0, r1, r2, r3,
                        sB + A_PL + (wn * 32 + bq * 16 + lrow) * ROWB + ks * 32 + lcol);
                b[2 * bq + 0][0] = r0; b[2 * bq + 0][1] = r2;
                b[2 * bq + 1][0] = r1; b[2 * bq + 1][1] = r3;
            }
#pragma unroll
            for (int mi = 0; mi < 4; mi++)
#pragma unroll
                for (int ni = 0; ni < 4; ni++)
                    mma_bf16(acc[mi][ni], aH[mi], b[ni]);
        }
        if (kc + 1 < KCH) __syncthreads();      // all reads of stage kc&1 done
    }

    // epilogue
#pragma unroll
    for (int mi = 0; mi < 4; mi++) {
#pragma unroll
        for (int ni = 0; ni < 4; ni++) {
            const int r = m0 + wm * 64 + mi * 16 + (lane >> 2);
            const int c = n0 + wn * 32 + ni * 8 + (lane & 3) * 2;
            const float bx = bias[c], by = bias[c + 1];
            float2 o0, o1;
            o0.x = epi_f<EPI>(acc[mi][ni][0] + bx);
            o0.y = epi_f<EPI>(acc[mi][ni][1] + by);
            o1.x = epi_f<EPI>(acc[mi][ni][2] + bx);
            o1.y = epi_f<EPI>(acc[mi][ni][3] + by);
            *(float2*)(C + (size_t)r * HDIM + c)       = o0;
            *(float2*)(C + (size_t)(r + 8) * HDIM + c) = o1;
        }
    }
}

// ---------------- beta projection: sigmoid(A @ Wb^T + bb), N=16 -------------
#define BROWS  64
#define BSTA   (BROWS * ROWB)        // 5120
#define BSTB   (16 * ROWB)           // 1280
#define BSTAGE (BSTA + BSTB)
#define BKTOT  96
#define BNSTG  3

__global__ __launch_bounds__(128, 4)
void beta_mma(const __nv_bfloat16* __restrict__ Ah, const __nv_bfloat16* __restrict__ Al,
              const __nv_bfloat16* __restrict__ Wh, const __nv_bfloat16* __restrict__ Wl,
              const float* __restrict__ bb, float* __restrict__ Bout)
{
    extern __shared__ char smem[];
    const uint32_t sb = smem_u32(smem);
    const int tid  = threadIdx.x;
    const int lane = tid & 31;
    const int warp = tid >> 5;
    const int m0   = blockIdx.x * BROWS;

    auto load_stage = [&](int kc, int st) {
        const int ph = kc >> 5;
        const __nv_bfloat16* As = (ph == 1) ? Al : Ah;
        const __nv_bfloat16* Ws = (ph == 2) ? Wl : Wh;
        const int k0 = (kc & 31) * 32;
        const uint32_t sA = sb + st * BSTAGE;
        const uint32_t sB = sA + BSTA;
#pragma unroll
        for (int i = 0; i < 2; i++) {
            const int idx = tid + i * 128;
            const int row = idx >> 2, c = idx & 3;
            cp16(sA + row * ROWB + c * 16, As + (size_t)(m0 + row) * HDIM + k0 + c * 8);
        }
        if (tid < 64) {
            const int row = tid >> 2, c = tid & 3;
            cp16(sB + row * ROWB + c * 16, Ws + (size_t)row * HDIM + k0 + c * 8);
        }
        cp_commit();
    };

    float acc[2][4];
#pragma unroll
    for (int i = 0; i < 2; i++)
#pragma unroll
        for (int k = 0; k < 4; k++) acc[i][k] = 0.f;

    load_stage(0, 0);
    load_stage(1, 1);

    for (int kc = 0; kc < BKTOT; kc++) {
        cp_wait<1>();
        __syncthreads();
        if (kc + 2 < BKTOT) load_stage(kc + 2, (kc + 2) % BNSTG);
        else                cp_commit();

        const uint32_t sA = sb + (kc % BNSTG) * BSTAGE;
        const uint32_t sB = sA + BSTA;
        const uint32_t lrow = lane & 15;
        const uint32_t lcol = (lane >> 4) * 16;

#pragma unroll
        for (int ks = 0; ks < 2; ks++) {
            uint32_t a[4], b[2][2];
            ldsm_x4(a[0], a[1], a[2], a[3],
                    sA + (warp * 16 + lrow) * ROWB + ks * 32 + lcol);
            uint32_t r0, r1, r2, r3;
            ldsm_x4(r0, r1, r2, r3, sB + lrow * ROWB + ks * 32 + lcol);
            b[0][0] = r0; b[0][1] = r2;
            b[1][0] = r1; b[1][1] = r3;
            mma_bf16(acc[0], a, b[0]);
            mma_bf16(acc[1], a, b[1]);
        }
    }

#pragma unroll
    for (int ni = 0; ni < 2; ni++) {
        const int r = m0 + warp * 16 + (lane >> 2);
        const int c = ni * 8 + (lane & 3) * 2;
        const float bx = bb[c], by = bb[c + 1];
        float2 o0, o1;
        o0.x = 1.f / (1.f + expf(-(acc[ni][0] + bx)));
        o0.y = 1.f / (1.f + expf(-(acc[ni][1] + by)));
        o1.x = 1.f / (1.f + expf(-(acc[ni][2] + bx)));
        o1.y = 1.f / (1.f + expf(-(acc[ni][3] + by)));
        *(float2*)(Bout + (size_t)r * NHEADS + c)       = o0;
        *(float2*)(Bout + (size_t)(r + 8) * NHEADS + c) = o1;
    }
}

// ---------------- delta-rule diagonal scan: s <- a*s + c --------------------
__global__ __launch_bounds__(64)
void scan_kernel(const float* __restrict__ Pq, const float* __restrict__ Pk,
                 const float* __restrict__ Vb, const float* __restrict__ Bs,
                 __nv_bfloat16* __restrict__ Yhi, __nv_bfloat16* __restrict__ Ylo)
{
    const int bh = blockIdx.x;
    const int d  = threadIdx.x;
    const size_t base = (size_t)(bh >> 4) * SEQ * HDIM + (size_t)(bh & 15) * 64 + d;
    const float* pk = Pk + base;
    const float* pq = Pq + base;
    const float* vv = Vb + base;
    __nv_bfloat16* yh = Yhi + base;
    __nv_bfloat16* yl = Ylo + base;
    const float* bp = Bs + (size_t)(bh >> 4) * SEQ * NHEADS + (bh & 15);

    float rpk[16], rpq[16], rv[16], rb[16];
#pragma unroll
    for (int j = 0; j < 16; j++) {
        const size_t o = (size_t)j * HDIM;
        rpk[j] = pk[o]; rpq[j] = pq[o]; rv[j] = vv[o];
        rb[j]  = bp[(size_t)j * NHEADS];
    }

    float s = 0.f;
    for (int t0 = 0; t0 < SEQ; t0 += 16) {
#pragma unroll
        for (int j = 0; j < 16; j++) {
            const int t = t0 + j;
            const float a = 1.f - rb[j] * rpk[j] * rpk[j];
            const float c = rb[j] * rv[j] * rpk[j];
            const float q = rpq[j];
            const int tn = t + 16;
            if (tn < SEQ) {
                const size_t o = (size_t)tn * HDIM;
                rpk[j] = pk[o]; rpq[j] = pq[o]; rv[j] = vv[o];
                rb[j]  = bp[(size_t)tn * NHEADS];
            }
            s = fmaf(a, s, c);
            const float y = s * q;
            const __nv_bfloat16 h = __float2bfloat16(y);
            yh[(size_t)t * HDIM] = h;
            yl[(size_t)t * HDIM] = __float2bfloat16(y - __bfloat162float(h));
        }
    }
}

// ---------------- launch -----------------------------------------------------
extern "C" void kernel_launch(void* const* d_in, const int* in_sizes, int n_in,
                              void* d_out, int out_size)
{
    const float* query = (const float*)d_in[0];
    const float* key   = (const float*)d_in[1];
    const float* value = (const float*)d_in[2];
    const float* beta  = (const float*)d_in[3];
    const float* Wq    = (const float*)d_in[4];
    const float* bq    = (const float*)d_in[5];
    const float* Wk    = (const float*)d_in[6];
    const float* bk    = (const float*)d_in[7];
    const float* Wv    = (const float*)d_in[8];
    const float* bv    = (const float*)d_in[9];
    const float* Wb    = (const float*)d_in[10];
    const float* bb    = (const float*)d_in[11];
    const float* Wo    = (const float*)d_in[12];
    const float* bo    = (const float*)d_in[13];
    float* out = (float*)d_out;

    __nv_bfloat16 *pAhi, *pAlo, *pWqh, *pWql, *pWkh, *pWkl, *pWvh, *pWvl, *pWoh, *pWol, *pWbh, *pWbl;
    float *pPq, *pPk, *pV, *pB;
    cudaGetSymbolAddress((void**)&pAhi, g_Ahi);
    cudaGetSymbolAddress((void**)&pAlo, g_Alo);
    cudaGetSymbolAddress((void**)&pWqh, g_Wqhi);
    cudaGetSymbolAddress((void**)&pWql, g_Wqlo);
    cudaGetSymbolAddress((void**)&pWkh, g_Wkhi);
    cudaGetSymbolAddress((void**)&pWkl, g_Wklo);
    cudaGetSymbolAddress((void**)&pWvh, g_Wvhi);
    cudaGetSymbolAddress((void**)&pWvl, g_Wvlo);
    cudaGetSymbolAddress((void**)&pWoh, g_Wohi);
    cudaGetSymbolAddress((void**)&pWol, g_Wolo);
    cudaGetSymbolAddress((void**)&pWbh, g_Wbhi);
    cudaGetSymbolAddress((void**)&pWbl, g_Wblo);
    cudaGetSymbolAddress((void**)&pPq, g_Pq);
    cudaGetSymbolAddress((void**)&pPk, g_Pk);
    cudaGetSymbolAddress((void**)&pV,  g_V);
    cudaGetSymbolAddress((void**)&pB,  g_B);

    const int SMEM_GEMM = 2 * STAGEB;            // 81920 -> 2 CTAs/SM
    const int SMEM_BETA = BNSTG * BSTAGE;        // 19200
    cudaFuncSetAttribute(gemm_mma<0>, cudaFuncAttributeMaxDynamicSharedMemorySize, SMEM_GEMM);
    cudaFuncSetAttribute(gemm_mma<1>, cudaFuncAttributeMaxDynamicSharedMemorySize, SMEM_GEMM);
    cudaFuncSetAttribute(beta_mma,    cudaFuncAttributeMaxDynamicSharedMemorySize, SMEM_BETA);

    const int N4A = MROWS * HDIM / 4;
    const int N4W = HDIM * HDIM / 4;
    const int N4B = NHEADS * HDIM / 4;

    const dim3 gBig(8, 64), blk(256);   // 512 CTAs

    // q projection + phi (gemm early so ncu -s captures a GEMM launch)
    conv_split<<<N4A / 256, 256>>>(query, pAhi, pAlo, N4A);
    conv_split<<<N4W / 256, 256>>>(Wq, pWqh, pWql, N4W);
    gemm_mma<1><<<gBig, blk, SMEM_GEMM>>>(pAhi, pAlo, pWqh, pWql, bq, pPq);
    // k projection + phi
    conv_split<<<N4W / 256, 256>>>(Wk, pWkh, pWkl, N4W);
    conv_split<<<N4A / 256, 256>>>(key, pAhi, pAlo, N4A);
    gemm_mma<1><<<gBig, blk, SMEM_GEMM>>>(pAhi, pAlo, pWkh, pWkl, bk, pPk);
    // v projection
    conv_split<<<N4A / 256, 256>>>(value, pAhi, pAlo, N4A);
    conv_split<<<N4W / 256, 256>>>(Wv, pWvh, pWvl, N4W);
    gemm_mma<0><<<gBig, blk, SMEM_GEMM>>>(pAhi, pAlo, pWvh, pWvl, bv, pV);
    // beta projection + sigmoid
    conv_split<<<N4A / 256, 256>>>(beta, pAhi, pAlo, N4A);
    conv_split<<<N4B / 256, 256>>>(Wb, pWbh, pWbl, N4B);
    beta_mma<<<MROWS / BROWS, 128, SMEM_BETA>>>(pAhi, pAlo, pWbh, pWbl, bb, pB);
    // scan (emits split-bf16 Y directly into the GEMM input buffers)
    scan_kernel<<<BATCH * NHEADS, 64>>>(pPq, pPk, pV, pB, pAhi, pAlo);
    // output projection
    conv_split<<<N4W / 256, 256>>>(Wo, pWoh, pWol, N4W);
    gemm_mma<0><<<gBig, blk, SMEM_GEMM>>>(pAhi, pAlo, pWoh, pWol, bo, out);
}

// round 15
// speedup vs baseline: 3.2078x; 1.3044x over previous
#include <cuda_runtime.h>
#include <cuda_bf16.h>
#include <cuda_fp16.h>
#include <math.h>
#include <stdint.h>

#define BATCH   4
#define SEQ     2048
#define HDIM    1024
#define NHEADS  16
#define MROWS   8192

// ---------------- scratch (device globals; no runtime allocation) -----------
__device__ __nv_bfloat16 g_Ahi[(size_t)MROWS * HDIM];   // bf16 hi OR fp16 plane
__device__ __nv_bfloat16 g_Alo[(size_t)MROWS * HDIM];
__device__ __nv_bfloat16 g_Wqhi[(size_t)HDIM * HDIM];
__device__ __nv_bfloat16 g_Wqlo[(size_t)HDIM * HDIM];
__device__ __nv_bfloat16 g_Wkhi[(size_t)HDIM * HDIM];
__device__ __nv_bfloat16 g_Wklo[(size_t)HDIM * HDIM];
__device__ __nv_bfloat16 g_Wvhi[(size_t)HDIM * HDIM];   // fp16 plane for Wv
__device__ __nv_bfloat16 g_Wohi[(size_t)HDIM * HDIM];   // fp16 plane for Wo
__device__ __nv_bfloat16 g_Wbhi[(size_t)NHEADS * HDIM];
__device__ __nv_bfloat16 g_Wblo[(size_t)NHEADS * HDIM];
__device__ float g_Pq[(size_t)MROWS * HDIM];
__device__ float g_Pk[(size_t)MROWS * HDIM];
__device__ float g_V [(size_t)MROWS * HDIM];
__device__ float g_B [(size_t)MROWS * NHEADS];

// ---------------- baseline-PTX helpers --------------------------------------
__device__ __forceinline__ uint32_t smem_u32(const void* p) {
    uint32_t a;
    asm("{ .reg .u64 t; cvta.to.shared.u64 t, %1; cvt.u32.u64 %0, t; }" : "=r"(a) : "l"(p));
    return a;
}
__device__ __forceinline__ void cp16(uint32_t dst, const void* src) {
    asm volatile("cp.async.cg.shared.global [%0], [%1], 16;\n" :: "r"(dst), "l"(src) : "memory");
}
__device__ __forceinline__ void cp_commit() {
    asm volatile("cp.async.commit_group;\n" ::: "memory");
}
template<int N> __device__ __forceinline__ void cp_wait() {
    asm volatile("cp.async.wait_group %0;\n" :: "n"(N) : "memory");
}
__device__ __forceinline__ void ldsm_x4(uint32_t& r0, uint32_t& r1, uint32_t& r2, uint32_t& r3,
                                        uint32_t addr) {
    asm volatile("ldmatrix.sync.aligned.m8n8.x4.shared.b16 {%0,%1,%2,%3}, [%4];"
                 : "=r"(r0), "=r"(r1), "=r"(r2), "=r"(r3) : "r"(addr));
}
__device__ __forceinline__ void mma_bf16(float* c, const uint32_t* a, const uint32_t* b) {
    asm volatile(
        "mma.sync.aligned.m16n8k16.row.col.f32.bf16.bf16.f32 "
        "{%0,%1,%2,%3}, {%4,%5,%6,%7}, {%8,%9}, {%0,%1,%2,%3};"
        : "+f"(c[0]), "+f"(c[1]), "+f"(c[2]), "+f"(c[3])
        : "r"(a[0]), "r"(a[1]), "r"(a[2]), "r"(a[3]), "r"(b[0]), "r"(b[1]));
}
__device__ __forceinline__ void mma_f16(float* c, const uint32_t* a, const uint32_t* b) {
    asm volatile(
        "mma.sync.aligned.m16n8k16.row.col.f32.f16.f16.f32 "
        "{%0,%1,%2,%3}, {%4,%5,%6,%7}, {%8,%9}, {%0,%1,%2,%3};"
        : "+f"(c[0]), "+f"(c[1]), "+f"(c[2]), "+f"(c[3])
        : "r"(a[0]), "r"(a[1]), "r"(a[2]), "r"(a[3]), "r"(b[0]), "r"(b[1]));
}

// ---------------- conversions ------------------------------------------------
__global__ __launch_bounds__(256)
void conv_split(const float* __restrict__ x, __nv_bfloat16* __restrict__ hi,
                __nv_bfloat16* __restrict__ lo, int n4)
{
    int i = blockIdx.x * blockDim.x + threadIdx.x;
    if (i >= n4) return;
    float4 v = ((const float4*)x)[i];
    __nv_bfloat16 h0 = __float2bfloat16(v.x);
    __nv_bfloat16 h1 = __float2bfloat16(v.y);
    __nv_bfloat16 h2 = __float2bfloat16(v.z);
    __nv_bfloat16 h3 = __float2bfloat16(v.w);
    __nv_bfloat16 l0 = __float2bfloat16(v.x - __bfloat162float(h0));
    __nv_bfloat16 l1 = __float2bfloat16(v.y - __bfloat162float(h1));
    __nv_bfloat16 l2 = __float2bfloat16(v.z - __bfloat162float(h2));
    __nv_bfloat16 l3 = __float2bfloat16(v.w - __bfloat162float(h3));
    ((__nv_bfloat162*)hi)[2 * i + 0] = __halves2bfloat162(h0, h1);
    ((__nv_bfloat162*)hi)[2 * i + 1] = __halves2bfloat162(h2, h3);
    ((__nv_bfloat162*)lo)[2 * i + 0] = __halves2bfloat162(l0, l1);
    ((__nv_bfloat162*)lo)[2 * i + 1] = __halves2bfloat162(l2, l3);
}

__global__ __launch_bounds__(256)
void conv_half(const float* __restrict__ x, __half* __restrict__ h, int n4)
{
    int i = blockIdx.x * blockDim.x + threadIdx.x;
    if (i >= n4) return;
    float4 v = ((const float4*)x)[i];
    ((__half2*)h)[2 * i + 0] = __floats2half2_rn(v.x, v.y);
    ((__half2*)h)[2 * i + 1] = __floats2half2_rn(v.z, v.w);
}

// ---------------- epilogues --------------------------------------------------
template<int EPI> __device__ __forceinline__ float epi_f(float x) {
    if (EPI == 1) return x > 0.f ? x + 1.f : expf(x);
    if (EPI == 2) return 1.f / (1.f + expf(-x));
    return x;
}

#define ROWB    80                  // smem row stride: 64B data + 16B pad
#define A_PL    (128 * ROWB)        // 10240 bytes per plane
#define STAGEB  (4 * A_PL)          // 40960 (bf16 split: 4 planes)
#define STAGE16 (2 * A_PL)          // 20480 (fp16: 2 planes)
#define KCH     32

// ---------------- split-bf16 HMMA GEMM (3-pass, q/k path) -------------------
template<int EPI>
__global__ __launch_bounds__(256, 2)
void gemm_mma(const __nv_bfloat16* __restrict__ Ah, const __nv_bfloat16* __restrict__ Al,
              const __nv_bfloat16* __restrict__ Wh, const __nv_bfloat16* __restrict__ Wl,
              const float* __restrict__ bias, float* __restrict__ C)
{
    extern __shared__ char smem[];
    const uint32_t sb = smem_u32(smem);
    const int tid  = threadIdx.x;
    const int lane = tid & 31;
    const int warp = tid >> 5;
    const int wm   = warp >> 2;
    const int wn   = warp & 3;
    const int m0   = blockIdx.y * 128;
    const int n0   = blockIdx.x * 128;

    auto load_stage = [&](int kc, int st) {
        const int k0 = kc * 32;
        const uint32_t sA = sb + st * STAGEB;
        const uint32_t sB = sA + 2 * A_PL;
#pragma unroll
        for (int i = 0; i < 4; i++) {
            const int idx = tid + i * 256;
            const int pl  = idx >> 9;
            const int r   = (idx >> 2) & 127;
            const int c   = idx & 3;
            cp16(sA + pl * A_PL + r * ROWB + c * 16,
                 (pl ? Al : Ah) + (size_t)(m0 + r) * HDIM + k0 + c * 8);
        }
#pragma unroll
        for (int i = 0; i < 4; i++) {
            const int idx = tid + i * 256;
            const int pl  = idx >> 9;
            const int r   = (idx >> 2) & 127;
            const int c   = idx & 3;
            cp16(sB + pl * A_PL + r * ROWB + c * 16,
                 (pl ? Wl : Wh) + (size_t)(n0 + r) * HDIM + k0 + c * 8);
        }
        cp_commit();
    };

    float acc[4][4][4];
#pragma unroll
    for (int i = 0; i < 4; i++)
#pragma unroll
        for (int j = 0; j < 4; j++)
#pragma unroll
            for (int k = 0; k < 4; k++) acc[i][j][k] = 0.f;

    load_stage(0, 0);

    const uint32_t lrow = lane & 15;
    const uint32_t lcol = (lane >> 4) * 16;

    for (int kc = 0; kc < KCH; kc++) {
        if (kc + 1 < KCH) {
            load_stage(kc + 1, (kc + 1) & 1);
            cp_wait<1>();
        } else {
            cp_wait<0>();
        }
        __syncthreads();

        const uint32_t sA = sb + (kc & 1) * STAGEB;
        const uint32_t sB = sA + 2 * A_PL;

#pragma unroll
        for (int ks = 0; ks < 2; ks++) {
            uint32_t aH[4][4], aL[4][4], b[4][2];
#pragma unroll
            for (int mi = 0; mi < 4; mi++) {
                const uint32_t ra = (wm * 64 + mi * 16 + lrow) * ROWB + ks * 32 + lcol;
                ldsm_x4(aH[mi][0], aH[mi][1], aH[mi][2], aH[mi][3], sA + ra);
                ldsm_x4(aL[mi][0], aL[mi][1], aL[mi][2], aL[mi][3], sA + A_PL + ra);
            }
#pragma unroll
            for (int bq = 0; bq < 2; bq++) {
                uint32_t r0, r1, r2, r3;
                ldsm_x4(r0, r1, r2, r3,
                        sB + (wn * 32 + bq * 16 + lrow) * ROWB + ks * 32 + lcol);
                b[2 * bq + 0][0] = r0; b[2 * bq + 0][1] = r2;
                b[2 * bq + 1][0] = r1; b[2 * bq + 1][1] = r3;
            }
#pragma unroll
            for (int mi = 0; mi < 4; mi++)
#pragma unroll
                for (int ni = 0; ni < 4; ni++) {
                    mma_bf16(acc[mi][ni], aH[mi], b[ni]);
                    mma_bf16(acc[mi][ni], aL[mi], b[ni]);
                }
#pragma unroll
            for (int bq = 0; bq < 2; bq++) {
                uint32_t r0, r1, r2, r3;
                ldsm_x4(r0, r1, r2, r3,
                        sB + A_PL + (wn * 32 + bq * 16 + lrow) * ROWB + ks * 32 + lcol);
                b[2 * bq + 0][0] = r0; b[2 * bq + 0][1] = r2;
                b[2 * bq + 1][0] = r1; b[2 * bq + 1][1] = r3;
            }
#pragma unroll
            for (int mi = 0; mi < 4; mi++)
#pragma unroll
                for (int ni = 0; ni < 4; ni++)
                    mma_bf16(acc[mi][ni], aH[mi], b[ni]);
        }
        if (kc + 1 < KCH) __syncthreads();
    }

#pragma unroll
    for (int mi = 0; mi < 4; mi++) {
#pragma unroll
        for (int ni = 0; ni < 4; ni++) {
            const int r = m0 + wm * 64 + mi * 16 + (lane >> 2);
            const int c = n0 + wn * 32 + ni * 8 + (lane & 3) * 2;
            const float bx = bias[c], by = bias[c + 1];
            float2 o0, o1;
            o0.x = epi_f<EPI>(acc[mi][ni][0] + bx);
            o0.y = epi_f<EPI>(acc[mi][ni][1] + by);
            o1.x = epi_f<EPI>(acc[mi][ni][2] + bx);
            o1.y = epi_f<EPI>(acc[mi][ni][3] + by);
            *(float2*)(C + (size_t)r * HDIM + c)       = o0;
            *(float2*)(C + (size_t)(r + 8) * HDIM + c) = o1;
        }
    }
}

// ---------------- single-pass fp16 HMMA GEMM (v / out path) ----------------
__global__ __launch_bounds__(256, 2)
void gemm_f16(const __half* __restrict__ A16, const __half* __restrict__ W16,
              const float* __restrict__ bias, float* __restrict__ C)
{
    extern __shared__ char smem[];
    const uint32_t sb = smem_u32(smem);
    const int tid  = threadIdx.x;
    const int lane = tid & 31;
    const int warp = tid >> 5;
    const int wm   = warp >> 2;
    const int wn   = warp & 3;
    const int m0   = blockIdx.y * 128;
    const int n0   = blockIdx.x * 128;

    auto load_stage = [&](int kc, int st) {
        const int k0 = kc * 32;
        const uint32_t sA = sb + st * STAGE16;
        const uint32_t sB = sA + A_PL;
#pragma unroll
        for (int i = 0; i < 2; i++) {
            const int idx = tid + i * 256;
            const int r   = idx >> 2;
            const int c   = idx & 3;
            cp16(sA + r * ROWB + c * 16, A16 + (size_t)(m0 + r) * HDIM + k0 + c * 8);
        }
#pragma unroll
        for (int i = 0; i < 2; i++) {
            const int idx = tid + i * 256;
            const int r   = idx >> 2;
            const int c   = idx & 3;
            cp16(sB + r * ROWB + c * 16, W16 + (size_t)(n0 + r) * HDIM + k0 + c * 8);
        }
        cp_commit();
    };

    float acc[4][4][4];
#pragma unroll
    for (int i = 0; i < 4; i++)
#pragma unroll
        for (int j = 0; j < 4; j++)
#pragma unroll
            for (int k = 0; k < 4; k++) acc[i][j][k] = 0.f;

    load_stage(0, 0);

    const uint32_t lrow = lane & 15;
    const uint32_t lcol = (lane >> 4) * 16;

    for (int kc = 0; kc < KCH; kc++) {
        if (kc + 1 < KCH) {
            load_stage(kc + 1, (kc + 1) & 1);
            cp_wait<1>();
        } else {
            cp_wait<0>();
        }
        __syncthreads();

        const uint32_t sA = sb + (kc & 1) * STAGE16;
        const uint32_t sB = sA + A_PL;

#pragma unroll
        for (int ks = 0; ks < 2; ks++) {
            uint32_t a[4][4], b[4][2];
#pragma unroll
            for (int mi = 0; mi < 4; mi++) {
                const uint32_t ra = (wm * 64 + mi * 16 + lrow) * ROWB + ks * 32 + lcol;
                ldsm_x4(a[mi][0], a[mi][1], a[mi][2], a[mi][3], sA + ra);
            }
#pragma unroll
            for (int bq = 0; bq < 2; bq++) {
                uint32_t r0, r1, r2, r3;
                ldsm_x4(r0, r1, r2, r3,
                        sB + (wn * 32 + bq * 16 + lrow) * ROWB + ks * 32 + lcol);
                b[2 * bq + 0][0] = r0; b[2 * bq + 0][1] = r2;
                b[2 * bq + 1][0] = r1; b[2 * bq + 1][1] = r3;
            }
#pragma unroll
            for (int mi = 0; mi < 4; mi++)
#pragma unroll
                for (int ni = 0; ni < 4; ni++)
                    mma_f16(acc[mi][ni], a[mi], b[ni]);
        }
        if (kc + 1 < KCH) __syncthreads();
    }

#pragma unroll
    for (int mi = 0; mi < 4; mi++) {
#pragma unroll
        for (int ni = 0; ni < 4; ni++) {
            const int r = m0 + wm * 64 + mi * 16 + (lane >> 2);
            const int c = n0 + wn * 32 + ni * 8 + (lane & 3) * 2;
            const float bx = bias[c], by = bias[c + 1];
            float2 o0, o1;
            o0.x = acc[mi][ni][0] + bx;
            o0.y = acc[mi][ni][1] + by;
            o1.x = acc[mi][ni][2] + bx;
            o1.y = acc[mi][ni][3] + by;
            *(float2*)(C + (size_t)r * HDIM + c)       = o0;
            *(float2*)(C + (size_t)(r + 8) * HDIM + c) = o1;
        }
    }
}

// ---------------- beta projection: sigmoid(A @ Wb^T + bb), N=16 -------------
#define BROWS  64
#define BSTA   (BROWS * ROWB)
#define BSTB   (16 * ROWB)
#define BSTAGE (BSTA + BSTB)
#define BKTOT  96
#define BNSTG  3

__global__ __launch_bounds__(128, 4)
void beta_mma(const __nv_bfloat16* __restrict__ Ah, const __nv_bfloat16* __restrict__ Al,
              const __nv_bfloat16* __restrict__ Wh, const __nv_bfloat16* __restrict__ Wl,
              const float* __restrict__ bb, float* __restrict__ Bout)
{
    extern __shared__ char smem[];
    const uint32_t sb = smem_u32(smem);
    const int tid  = threadIdx.x;
    const int lane = tid & 31;
    const int warp = tid >> 5;
    const int m0   = blockIdx.x * BROWS;

    auto load_stage = [&](int kc, int st) {
        const int ph = kc >> 5;
        const __nv_bfloat16* As = (ph == 1) ? Al : Ah;
        const __nv_bfloat16* Ws = (ph == 2) ? Wl : Wh;
        const int k0 = (kc & 31) * 32;
        const uint32_t sA = sb + st * BSTAGE;
        const uint32_t sB = sA + BSTA;
#pragma unroll
        for (int i = 0; i < 2; i++) {
            const int idx = tid + i * 128;
            const int row = idx >> 2, c = idx & 3;
            cp16(sA + row * ROWB + c * 16, As + (size_t)(m0 + row) * HDIM + k0 + c * 8);
        }
        if (tid < 64) {
            const int row = tid >> 2, c = tid & 3;
            cp16(sB + row * ROWB + c * 16, Ws + (size_t)row * HDIM + k0 + c * 8);
        }
        cp_commit();
    };

    float acc[2][4];
#pragma unroll
    for (int i = 0; i < 2; i++)
#pragma unroll
        for (int k = 0; k < 4; k++) acc[i][k] = 0.f;

    load_stage(0, 0);
    load_stage(1, 1);

    for (int kc = 0; kc < BKTOT; kc++) {
        cp_wait<1>();
        __syncthreads();
        if (kc + 2 < BKTOT) load_stage(kc + 2, (kc + 2) % BNSTG);
        else                cp_commit();

        const uint32_t sA = sb + (kc % BNSTG) * BSTAGE;
        const uint32_t sB = sA + BSTA;
        const uint32_t lrow = lane & 15;
        const uint32_t lcol = (lane >> 4) * 16;

#pragma unroll
        for (int ks = 0; ks < 2; ks++) {
            uint32_t a[4], b[2][2];
            ldsm_x4(a[0], a[1], a[2], a[3],
                    sA + (warp * 16 + lrow) * ROWB + ks * 32 + lcol);
            uint32_t r0, r1, r2, r3;
            ldsm_x4(r0, r1, r2, r3, sB + lrow * ROWB + ks * 32 + lcol);
            b[0][0] = r0; b[0][1] = r2;
            b[1][0] = r1; b[1][1] = r3;
            mma_bf16(acc[0], a, b[0]);
            mma_bf16(acc[1], a, b[1]);
        }
    }

#pragma unroll
    for (int ni = 0; ni < 2; ni++) {
        const int r = m0 + warp * 16 + (lane >> 2);
        const int c = ni * 8 + (lane & 3) * 2;
        const float bx = bb[c], by = bb[c + 1];
        float2 o0, o1;
        o0.x = 1.f / (1.f + expf(-(acc[ni][0] + bx)));
        o0.y = 1.f / (1.f + expf(-(acc[ni][1] + by)));
        o1.x = 1.f / (1.f + expf(-(acc[ni][2] + bx)));
        o1.y = 1.f / (1.f + expf(-(acc[ni][3] + by)));
        *(float2*)(Bout + (size_t)r * NHEADS + c)       = o0;
        *(float2*)(Bout + (size_t)(r + 8) * NHEADS + c) = o1;
    }
}

// ---------------- delta-rule diagonal scan: s <- a*s + c --------------------
// Emits y directly as fp16 (single plane) for the out-projection.
__global__ __launch_bounds__(64)
void scan_kernel(const float* __restrict__ Pq, const float* __restrict__ Pk,
                 const float* __restrict__ Vb, const float* __restrict__ Bs,
                 __half* __restrict__ Yh)
{
    const int bh = blockIdx.x;
    const int d  = threadIdx.x;
    const size_t base = (size_t)(bh >> 4) * SEQ * HDIM + (size_t)(bh & 15) * 64 + d;
    const float* pk = Pk + base;
    const float* pq = Pq + base;
    const float* vv = Vb + base;
    __half* yh = Yh + base;
    const float* bp = Bs + (size_t)(bh >> 4) * SEQ * NHEADS + (bh & 15);

    float rpk[16], rpq[16], rv[16], rb[16];
#pragma unroll
    for (int j = 0; j < 16; j++) {
        const size_t o = (size_t)j * HDIM;
        rpk[j] = pk[o]; rpq[j] = pq[o]; rv[j] = vv[o];
        rb[j]  = bp[(size_t)j * NHEADS];
    }

    float s = 0.f;
    for (int t0 = 0; t0 < SEQ; t0 += 16) {
#pragma unroll
        for (int j = 0; j < 16; j++) {
            const int t = t0 + j;
            const float a = 1.f - rb[j] * rpk[j] * rpk[j];
            const float c = rb[j] * rv[j] * rpk[j];
            const float q = rpq[j];
            const int tn = t + 16;
            if (tn < SEQ) {
                const size_t o = (size_t)tn * HDIM;
                rpk[j] = pk[o]; rpq[j] = pq[o]; rv[j] = vv[o];
                rb[j]  = bp[(size_t)tn * NHEADS];
            }
            s = fmaf(a, s, c);
            yh[(size_t)t * HDIM] = __float2half_rn(s * q);
        }
    }
}

// ---------------- launch -----------------------------------------------------
extern "C" void kernel_launch(void* const* d_in, const int* in_sizes, int n_in,
                              void* d_out, int out_size)
{
    const float* query = (const float*)d_in[0];
    const float* key   = (const float*)d_in[1];
    const float* value = (const float*)d_in[2];
    const float* beta  = (const float*)d_in[3];
    const float* Wq    = (const float*)d_in[4];
    const float* bq    = (const float*)d_in[5];
    const float* Wk    = (const float*)d_in[6];
    const float* bk    = (const float*)d_in[7];
    const float* Wv    = (const float*)d_in[8];
    const float* bv    = (const float*)d_in[9];
    const float* Wb    = (const float*)d_in[10];
    const float* bb    = (const float*)d_in[11];
    const float* Wo    = (const float*)d_in[12];
    const float* bo    = (const float*)d_in[13];
    float* out = (float*)d_out;

    __nv_bfloat16 *pAhi, *pAlo, *pWqh, *pWql, *pWkh, *pWkl, *pWvh, *pWoh, *pWbh, *pWbl;
    float *pPq, *pPk, *pV, *pB;
    cudaGetSymbolAddress((void**)&pAhi, g_Ahi);
    cudaGetSymbolAddress((void**)&pAlo, g_Alo);
    cudaGetSymbolAddress((void**)&pWqh, g_Wqhi);
    cudaGetSymbolAddress((void**)&pWql, g_Wqlo);
    cudaGetSymbolAddress((void**)&pWkh, g_Wkhi);
    cudaGetSymbolAddress((void**)&pWkl, g_Wklo);
    cudaGetSymbolAddress((void**)&pWvh, g_Wvhi);
    cudaGetSymbolAddress((void**)&pWoh, g_Wohi);
    cudaGetSymbolAddress((void**)&pWbh, g_Wbhi);
    cudaGetSymbolAddress((void**)&pWbl, g_Wblo);
    cudaGetSymbolAddress((void**)&pPq, g_Pq);
    cudaGetSymbolAddress((void**)&pPk, g_Pk);
    cudaGetSymbolAddress((void**)&pV,  g_V);
    cudaGetSymbolAddress((void**)&pB,  g_B);

    const int SMEM_GEMM = 2 * STAGEB;            // 81920 -> 2 CTAs/SM
    const int SMEM_G16  = 2 * STAGE16;           // 40960
    const int SMEM_BETA = BNSTG * BSTAGE;
    cudaFuncSetAttribute(gemm_mma<0>, cudaFuncAttributeMaxDynamicSharedMemorySize, SMEM_GEMM);
    cudaFuncSetAttribute(gemm_mma<1>, cudaFuncAttributeMaxDynamicSharedMemorySize, SMEM_GEMM);
    cudaFuncSetAttribute(gemm_f16,    cudaFuncAttributeMaxDynamicSharedMemorySize, SMEM_G16);
    cudaFuncSetAttribute(beta_mma,    cudaFuncAttributeMaxDynamicSharedMemorySize, SMEM_BETA);

    const int N4A = MROWS * HDIM / 4;
    const int N4W = HDIM * HDIM / 4;
    const int N4B = NHEADS * HDIM / 4;

    const dim3 gBig(8, 64), blk(256);

    // q projection + phi  (3-pass bf16: scan-amplified error path)
    conv_split<<<N4A / 256, 256>>>(query, pAhi, pAlo, N4A);
    conv_split<<<N4W / 256, 256>>>(Wq, pWqh, pWql, N4W);
    gemm_mma<1><<<gBig, blk, SMEM_GEMM>>>(pAhi, pAlo, pWqh, pWql, bq, pPq);
    // k projection + phi  (3-pass bf16)
    conv_split<<<N4W / 256, 256>>>(Wk, pWkh, pWkl, N4W);
    conv_split<<<N4A / 256, 256>>>(key, pAhi, pAlo, N4A);
    gemm_mma<1><<<gBig, blk, SMEM_GEMM>>>(pAhi, pAlo, pWkh, pWkl, bk, pPk);
    // v projection  (1-pass fp16: linear, non-amplified path)
    conv_half<<<N4A / 256, 256>>>(value, (__half*)pAhi, N4A);
    conv_half<<<N4W / 256, 256>>>(Wv, (__half*)pWvh, N4W);
    gemm_f16<<<gBig, blk, SMEM_G16>>>((const __half*)pAhi, (const __half*)pWvh, bv, pV);
    // beta projection + sigmoid  (3-pass bf16)
    conv_split<<<N4A / 256, 256>>>(beta, pAhi, pAlo, N4A);
    conv_split<<<N4B / 256, 256>>>(Wb, pWbh, pWbl, N4B);
    beta_mma<<<MROWS / BROWS, 128, SMEM_BETA>>>(pAhi, pAlo, pWbh, pWbl, bb, pB);
    // scan -> fp16 Y directly into the fp16 GEMM input buffer
    scan_kernel<<<BATCH * NHEADS, 64>>>(pPq, pPk, pV, pB, (__half*)pAhi);
    // output projection  (1-pass fp16: terminal error path)
    conv_half<<<N4W / 256, 256>>>(Wo, (__half*)pWoh, N4W);
    gemm_f16<<<gBig, blk, SMEM_G16>>>((const __half*)pAhi, (const __half*)pWoh, bo, out);
}

// round 16
// speedup vs baseline: 3.8364x; 1.1960x over previous
#include <cuda_runtime.h>
#include <cuda_bf16.h>
#include <cuda_fp16.h>
#include <math.h>
#include <stdint.h>

#define BATCH   4
#define SEQ     2048
#define HDIM    1024
#define NHEADS  16
#define MROWS   8192

// ---------------- scratch (device globals; no runtime allocation) -----------
__device__ __nv_bfloat16 g_Ahi[(size_t)MROWS * HDIM];   // bf16 hi OR fp16 plane
__device__ __nv_bfloat16 g_Alo[(size_t)MROWS * HDIM];
__device__ __nv_bfloat16 g_Wq16[(size_t)HDIM * HDIM];   // fp16 plane for Wq
__device__ __nv_bfloat16 g_Wkhi[(size_t)HDIM * HDIM];
__device__ __nv_bfloat16 g_Wklo[(size_t)HDIM * HDIM];
__device__ __nv_bfloat16 g_Wv16[(size_t)HDIM * HDIM];   // fp16 plane for Wv
__device__ __nv_bfloat16 g_Wo16[(size_t)HDIM * HDIM];   // fp16 plane for Wo
__device__ __nv_bfloat16 g_Wbhi[(size_t)NHEADS * HDIM];
__device__ __nv_bfloat16 g_Wblo[(size_t)NHEADS * HDIM];
__device__ float g_Pq[(size_t)MROWS * HDIM];
__device__ float g_Pk[(size_t)MROWS * HDIM];
__device__ float g_V [(size_t)MROWS * HDIM];
__device__ float g_B [(size_t)MROWS * NHEADS];

// ---------------- baseline-PTX helpers --------------------------------------
__device__ __forceinline__ uint32_t smem_u32(const void* p) {
    uint32_t a;
    asm("{ .reg .u64 t; cvta.to.shared.u64 t, %1; cvt.u32.u64 %0, t; }" : "=r"(a) : "l"(p));
    return a;
}
__device__ __forceinline__ void cp16(uint32_t dst, const void* src) {
    asm volatile("cp.async.cg.shared.global [%0], [%1], 16;\n" :: "r"(dst), "l"(src) : "memory");
}
__device__ __forceinline__ void cp_commit() {
    asm volatile("cp.async.commit_group;\n" ::: "memory");
}
template<int N> __device__ __forceinline__ void cp_wait() {
    asm volatile("cp.async.wait_group %0;\n" :: "n"(N) : "memory");
}
__device__ __forceinline__ void ldsm_x4(uint32_t& r0, uint32_t& r1, uint32_t& r2, uint32_t& r3,
                                        uint32_t addr) {
    asm volatile("ldmatrix.sync.aligned.m8n8.x4.shared.b16 {%0,%1,%2,%3}, [%4];"
                 : "=r"(r0), "=r"(r1), "=r"(r2), "=r"(r3) : "r"(addr));
}
__device__ __forceinline__ void mma_bf16(float* c, const uint32_t* a, const uint32_t* b) {
    asm volatile(
        "mma.sync.aligned.m16n8k16.row.col.f32.bf16.bf16.f32 "
        "{%0,%1,%2,%3}, {%4,%5,%6,%7}, {%8,%9}, {%0,%1,%2,%3};"
        : "+f"(c[0]), "+f"(c[1]), "+f"(c[2]), "+f"(c[3])
        : "r"(a[0]), "r"(a[1]), "r"(a[2]), "r"(a[3]), "r"(b[0]), "r"(b[1]));
}
__device__ __forceinline__ void mma_f16(float* c, const uint32_t* a, const uint32_t* b) {
    asm volatile(
        "mma.sync.aligned.m16n8k16.row.col.f32.f16.f16.f32 "
        "{%0,%1,%2,%3}, {%4,%5,%6,%7}, {%8,%9}, {%0,%1,%2,%3};"
        : "+f"(c[0]), "+f"(c[1]), "+f"(c[2]), "+f"(c[3])
        : "r"(a[0]), "r"(a[1]), "r"(a[2]), "r"(a[3]), "r"(b[0]), "r"(b[1]));
}

// ---------------- conversions ------------------------------------------------
__global__ __launch_bounds__(256)
void conv_split(const float* __restrict__ x, __nv_bfloat16* __restrict__ hi,
                __nv_bfloat16* __restrict__ lo, int n4)
{
    int i = blockIdx.x * blockDim.x + threadIdx.x;
    if (i >= n4) return;
    float4 v = ((const float4*)x)[i];
    __nv_bfloat16 h0 = __float2bfloat16(v.x);
    __nv_bfloat16 h1 = __float2bfloat16(v.y);
    __nv_bfloat16 h2 = __float2bfloat16(v.z);
    __nv_bfloat16 h3 = __float2bfloat16(v.w);
    __nv_bfloat16 l0 = __float2bfloat16(v.x - __bfloat162float(h0));
    __nv_bfloat16 l1 = __float2bfloat16(v.y - __bfloat162float(h1));
    __nv_bfloat16 l2 = __float2bfloat16(v.z - __bfloat162float(h2));
    __nv_bfloat16 l3 = __float2bfloat16(v.w - __bfloat162float(h3));
    ((__nv_bfloat162*)hi)[2 * i + 0] = __halves2bfloat162(h0, h1);
    ((__nv_bfloat162*)hi)[2 * i + 1] = __halves2bfloat162(h2, h3);
    ((__nv_bfloat162*)lo)[2 * i + 0] = __halves2bfloat162(l0, l1);
    ((__nv_bfloat162*)lo)[2 * i + 1] = __halves2bfloat162(l2, l3);
}

__global__ __launch_bounds__(256)
void conv_half(const float* __restrict__ x, __half* __restrict__ h, int n4)
{
    int i = blockIdx.x * blockDim.x + threadIdx.x;
    if (i >= n4) return;
    float4 v = ((const float4*)x)[i];
    ((__half2*)h)[2 * i + 0] = __floats2half2_rn(v.x, v.y);
    ((__half2*)h)[2 * i + 1] = __floats2half2_rn(v.z, v.w);
}

// ---------------- epilogues --------------------------------------------------
template<int EPI> __device__ __forceinline__ float epi_f(float x) {
    if (EPI == 1) return x > 0.f ? x + 1.f : expf(x);
    if (EPI == 2) return 1.f / (1.f + expf(-x));
    return x;
}

#define ROWB    80                  // smem row stride: 64B data + 16B pad
#define A_PL    (128 * ROWB)        // 10240 bytes per plane
#define STAGEB  (4 * A_PL)          // 40960 (bf16 split: 4 planes)
#define STAGE16 (2 * A_PL)          // 20480 (fp16: 2 planes)
#define KCH     32

// ---------------- split-bf16 HMMA GEMM (3-pass, k path) ---------------------
template<int EPI>
__global__ __launch_bounds__(256, 2)
void gemm_mma(const __nv_bfloat16* __restrict__ Ah, const __nv_bfloat16* __restrict__ Al,
              const __nv_bfloat16* __restrict__ Wh, const __nv_bfloat16* __restrict__ Wl,
              const float* __restrict__ bias, float* __restrict__ C)
{
    extern __shared__ char smem[];
    const uint32_t sb = smem_u32(smem);
    const int tid  = threadIdx.x;
    const int lane = tid & 31;
    const int warp = tid >> 5;
    const int wm   = warp >> 2;
    const int wn   = warp & 3;
    const int m0   = blockIdx.y * 128;
    const int n0   = blockIdx.x * 128;

    auto load_stage = [&](int kc, int st) {
        const int k0 = kc * 32;
        const uint32_t sA = sb + st * STAGEB;
        const uint32_t sB = sA + 2 * A_PL;
#pragma unroll
        for (int i = 0; i < 4; i++) {
            const int idx = tid + i * 256;
            const int pl  = idx >> 9;
            const int r   = (idx >> 2) & 127;
            const int c   = idx & 3;
            cp16(sA + pl * A_PL + r * ROWB + c * 16,
                 (pl ? Al : Ah) + (size_t)(m0 + r) * HDIM + k0 + c * 8);
        }
#pragma unroll
        for (int i = 0; i < 4; i++) {
            const int idx = tid + i * 256;
            const int pl  = idx >> 9;
            const int r   = (idx >> 2) & 127;
            const int c   = idx & 3;
            cp16(sB + pl * A_PL + r * ROWB + c * 16,
                 (pl ? Wl : Wh) + (size_t)(n0 + r) * HDIM + k0 + c * 8);
        }
        cp_commit();
    };

    float acc[4][4][4];
#pragma unroll
    for (int i = 0; i < 4; i++)
#pragma unroll
        for (int j = 0; j < 4; j++)
#pragma unroll
            for (int k = 0; k < 4; k++) acc[i][j][k] = 0.f;

    load_stage(0, 0);

    const uint32_t lrow = lane & 15;
    const uint32_t lcol = (lane >> 4) * 16;

    for (int kc = 0; kc < KCH; kc++) {
        if (kc + 1 < KCH) {
            load_stage(kc + 1, (kc + 1) & 1);
            cp_wait<1>();
        } else {
            cp_wait<0>();
        }
        __syncthreads();

        const uint32_t sA = sb + (kc & 1) * STAGEB;
        const uint32_t sB = sA + 2 * A_PL;

#pragma unroll
        for (int ks = 0; ks < 2; ks++) {
            uint32_t aH[4][4], aL[4][4], b[4][2];
#pragma unroll
            for (int mi = 0; mi < 4; mi++) {
                const uint32_t ra = (wm * 64 + mi * 16 + lrow) * ROWB + ks * 32 + lcol;
                ldsm_x4(aH[mi][0], aH[mi][1], aH[mi][2], aH[mi][3], sA + ra);
                ldsm_x4(aL[mi][0], aL[mi][1], aL[mi][2], aL[mi][3], sA + A_PL + ra);
            }
#pragma unroll
            for (int bq = 0; bq < 2; bq++) {
                uint32_t r0, r1, r2, r3;
                ldsm_x4(r0, r1, r2, r3,
                        sB + (wn * 32 + bq * 16 + lrow) * ROWB + ks * 32 + lcol);
                b[2 * bq + 0][0] = r0; b[2 * bq + 0][1] = r2;
                b[2 * bq + 1][0] = r1; b[2 * bq + 1][1] = r3;
            }
#pragma unroll
            for (int mi = 0; mi < 4; mi++)
#pragma unroll
                for (int ni = 0; ni < 4; ni++) {
                    mma_bf16(acc[mi][ni], aH[mi], b[ni]);
                    mma_bf16(acc[mi][ni], aL[mi], b[ni]);
                }
#pragma unroll
            for (int bq = 0; bq < 2; bq++) {
                uint32_t r0, r1, r2, r3;
                ldsm_x4(r0, r1, r2, r3,
                        sB + A_PL + (wn * 32 + bq * 16 + lrow) * ROWB + ks * 32 + lcol);
                b[2 * bq + 0][0] = r0; b[2 * bq + 0][1] = r2;
                b[2 * bq + 1][0] = r1; b[2 * bq + 1][1] = r3;
            }
#pragma unroll
            for (int mi = 0; mi < 4; mi++)
#pragma unroll
                for (int ni = 0; ni < 4; ni++)
                    mma_bf16(acc[mi][ni], aH[mi], b[ni]);
        }
        if (kc + 1 < KCH) __syncthreads();
    }

#pragma unroll
    for (int mi = 0; mi < 4; mi++) {
#pragma unroll
        for (int ni = 0; ni < 4; ni++) {
            const int r = m0 + wm * 64 + mi * 16 + (lane >> 2);
            const int c = n0 + wn * 32 + ni * 8 + (lane & 3) * 2;
            const float bx = bias[c], by = bias[c + 1];
            float2 o0, o1;
            o0.x = epi_f<EPI>(acc[mi][ni][0] + bx);
            o0.y = epi_f<EPI>(acc[mi][ni][1] + by);
            o1.x = epi_f<EPI>(acc[mi][ni][2] + bx);
            o1.y = epi_f<EPI>(acc[mi][ni][3] + by);
            *(float2*)(C + (size_t)r * HDIM + c)       = o0;
            *(float2*)(C + (size_t)(r + 8) * HDIM + c) = o1;
        }
    }
}

// ---------------- single-pass fp16 HMMA GEMM (q / v / out paths) ------------
template<int EPI>
__global__ __launch_bounds__(256, 2)
void gemm_f16(const __half* __restrict__ A16, const __half* __restrict__ W16,
              const float* __restrict__ bias, float* __restrict__ C)
{
    extern __shared__ char smem[];
    const uint32_t sb = smem_u32(smem);
    const int tid  = threadIdx.x;
    const int lane = tid & 31;
    const int warp = tid >> 5;
    const int wm   = warp >> 2;
    const int wn   = warp & 3;
    const int m0   = blockIdx.y * 128;
    const int n0   = blockIdx.x * 128;

    auto load_stage = [&](int kc, int st) {
        const int k0 = kc * 32;
        const uint32_t sA = sb + st * STAGE16;
        const uint32_t sB = sA + A_PL;
#pragma unroll
        for (int i = 0; i < 2; i++) {
            const int idx = tid + i * 256;
            const int r   = idx >> 2;
            const int c   = idx & 3;
            cp16(sA + r * ROWB + c * 16, A16 + (size_t)(m0 + r) * HDIM + k0 + c * 8);
        }
#pragma unroll
        for (int i = 0; i < 2; i++) {
            const int idx = tid + i * 256;
            const int r   = idx >> 2;
            const int c   = idx & 3;
            cp16(sB + r * ROWB + c * 16, W16 + (size_t)(n0 + r) * HDIM + k0 + c * 8);
        }
        cp_commit();
    };

    float acc[4][4][4];
#pragma unroll
    for (int i = 0; i < 4; i++)
#pragma unroll
        for (int j = 0; j < 4; j++)
#pragma unroll
            for (int k = 0; k < 4; k++) acc[i][j][k] = 0.f;

    load_stage(0, 0);

    const uint32_t lrow = lane & 15;
    const uint32_t lcol = (lane >> 4) * 16;

    for (int kc = 0; kc < KCH; kc++) {
        if (kc + 1 < KCH) {
            load_stage(kc + 1, (kc + 1) & 1);
            cp_wait<1>();
        } else {
            cp_wait<0>();
        }
        __syncthreads();

        const uint32_t sA = sb + (kc & 1) * STAGE16;
        const uint32_t sB = sA + A_PL;

#pragma unroll
        for (int ks = 0; ks < 2; ks++) {
            uint32_t a[4][4], b[4][2];
#pragma unroll
            for (int mi = 0; mi < 4; mi++) {
                const uint32_t ra = (wm * 64 + mi * 16 + lrow) * ROWB + ks * 32 + lcol;
                ldsm_x4(a[mi][0], a[mi][1], a[mi][2], a[mi][3], sA + ra);
            }
#pragma unroll
            for (int bq = 0; bq < 2; bq++) {
                uint32_t r0, r1, r2, r3;
                ldsm_x4(r0, r1, r2, r3,
                        sB + (wn * 32 + bq * 16 + lrow) * ROWB + ks * 32 + lcol);
                b[2 * bq + 0][0] = r0; b[2 * bq + 0][1] = r2;
                b[2 * bq + 1][0] = r1; b[2 * bq + 1][1] = r3;
            }
#pragma unroll
            for (int mi = 0; mi < 4; mi++)
#pragma unroll
                for (int ni = 0; ni < 4; ni++)
                    mma_f16(acc[mi][ni], a[mi], b[ni]);
        }
        if (kc + 1 < KCH) __syncthreads();
    }

#pragma unroll
    for (int mi = 0; mi < 4; mi++) {
#pragma unroll
        for (int ni = 0; ni < 4; ni++) {
            const int r = m0 + wm * 64 + mi * 16 + (lane >> 2);
            const int c = n0 + wn * 32 + ni * 8 + (lane & 3) * 2;
            const float bx = bias[c], by = bias[c + 1];
            float2 o0, o1;
            o0.x = epi_f<EPI>(acc[mi][ni][0] + bx);
            o0.y = epi_f<EPI>(acc[mi][ni][1] + by);
            o1.x = epi_f<EPI>(acc[mi][ni][2] + bx);
            o1.y = epi_f<EPI>(acc[mi][ni][3] + by);
            *(float2*)(C + (size_t)r * HDIM + c)       = o0;
            *(float2*)(C + (size_t)(r + 8) * HDIM + c) = o1;
        }
    }
}

// ---------------- beta projection: sigmoid(A @ Wb^T + bb), N=16 -------------
#define BROWS  64
#define BSTA   (BROWS * ROWB)
#define BSTB   (16 * ROWB)
#define BSTAGE (BSTA + BSTB)
#define BKTOT  96
#define BNSTG  3

__global__ __launch_bounds__(128, 4)
void beta_mma(const __nv_bfloat16* __restrict__ Ah, const __nv_bfloat16* __restrict__ Al,
              const __nv_bfloat16* __restrict__ Wh, const __nv_bfloat16* __restrict__ Wl,
              const float* __restrict__ bb, float* __restrict__ Bout)
{
    extern __shared__ char smem[];
    const uint32_t sb = smem_u32(smem);
    const int tid  = threadIdx.x;
    const int lane = tid & 31;
    const int warp = tid >> 5;
    const int m0   = blockIdx.x * BROWS;

    auto load_stage = [&](int kc, int st) {
        const int ph = kc >> 5;
        const __nv_bfloat16* As = (ph == 1) ? Al : Ah;
        const __nv_bfloat16* Ws = (ph == 2) ? Wl : Wh;
        const int k0 = (kc & 31) * 32;
        const uint32_t sA = sb + st * BSTAGE;
        const uint32_t sB = sA + BSTA;
#pragma unroll
        for (int i = 0; i < 2; i++) {
            const int idx = tid + i * 128;
            const int row = idx >> 2, c = idx & 3;
            cp16(sA + row * ROWB + c * 16, As + (size_t)(m0 + row) * HDIM + k0 + c * 8);
        }
        if (tid < 64) {
            const int row = tid >> 2, c = tid & 3;
            cp16(sB + row * ROWB + c * 16, Ws + (size_t)row * HDIM + k0 + c * 8);
        }
        cp_commit();
    };

    float acc[2][4];
#pragma unroll
    for (int i = 0; i < 2; i++)
#pragma unroll
        for (int k = 0; k < 4; k++) acc[i][k] = 0.f;

    load_stage(0, 0);
    load_stage(1, 1);

    for (int kc = 0; kc < BKTOT; kc++) {
        cp_wait<1>();
        __syncthreads();
        if (kc + 2 < BKTOT) load_stage(kc + 2, (kc + 2) % BNSTG);
        else                cp_commit();

        const uint32_t sA = sb + (kc % BNSTG) * BSTAGE;
        const uint32_t sB = sA + BSTA;
        const uint32_t lrow = lane & 15;
        const uint32_t lcol = (lane >> 4) * 16;

#pragma unroll
        for (int ks = 0; ks < 2; ks++) {
            uint32_t a[4], b[2][2];
            ldsm_x4(a[0], a[1], a[2], a[3],
                    sA + (warp * 16 + lrow) * ROWB + ks * 32 + lcol);
            uint32_t r0, r1, r2, r3;
            ldsm_x4(r0, r1, r2, r3, sB + lrow * ROWB + ks * 32 + lcol);
            b[0][0] = r0; b[0][1] = r2;
            b[1][0] = r1; b[1][1] = r3;
            mma_bf16(acc[0], a, b[0]);
            mma_bf16(acc[1], a, b[1]);
        }
    }

#pragma unroll
    for (int ni = 0; ni < 2; ni++) {
        const int r = m0 + warp * 16 + (lane >> 2);
        const int c = ni * 8 + (lane & 3) * 2;
        const float bx = bb[c], by = bb[c + 1];
        float2 o0, o1;
        o0.x = 1.f / (1.f + expf(-(acc[ni][0] + bx)));
        o0.y = 1.f / (1.f + expf(-(acc[ni][1] + by)));
        o1.x = 1.f / (1.f + expf(-(acc[ni][2] + bx)));
        o1.y = 1.f / (1.f + expf(-(acc[ni][3] + by)));
        *(float2*)(Bout + (size_t)r * NHEADS + c)       = o0;
        *(float2*)(Bout + (size_t)(r + 8) * NHEADS + c) = o1;
    }
}

// ---------------- delta-rule diagonal scan: s <- a*s + c --------------------
// Emits y directly as fp16 (single plane) for the out-projection.
__global__ __launch_bounds__(64)
void scan_kernel(const float* __restrict__ Pq, const float* __restrict__ Pk,
                 const float* __restrict__ Vb, const float* __restrict__ Bs,
                 __half* __restrict__ Yh)
{
    const int bh = blockIdx.x;
    const int d  = threadIdx.x;
    const size_t base = (size_t)(bh >> 4) * SEQ * HDIM + (size_t)(bh & 15) * 64 + d;
    const float* pk = Pk + base;
    const float* pq = Pq + base;
    const float* vv = Vb + base;
    __half* yh = Yh + base;
    const float* bp = Bs + (size_t)(bh >> 4) * SEQ * NHEADS + (bh & 15);

    float rpk[16], rpq[16], rv[16], rb[16];
#pragma unroll
    for (int j = 0; j < 16; j++) {
        const size_t o = (size_t)j * HDIM;
        rpk[j] = pk[o]; rpq[j] = pq[o]; rv[j] = vv[o];
        rb[j]  = bp[(size_t)j * NHEADS];
    }

    float s = 0.f;
    for (int t0 = 0; t0 < SEQ; t0 += 16) {
#pragma unroll
        for (int j = 0; j < 16; j++) {
            const int t = t0 + j;
            const float a = 1.f - rb[j] * rpk[j] * rpk[j];
            const float c = rb[j] * rv[j] * rpk[j];
            const float q = rpq[j];
            const int tn = t + 16;
            if (tn < SEQ) {
                const size_t o = (size_t)tn * HDIM;
                rpk[j] = pk[o]; rpq[j] = pq[o]; rv[j] = vv[o];
                rb[j]  = bp[(size_t)tn * NHEADS];
            }
            s = fmaf(a, s, c);
            yh[(size_t)t * HDIM] = __float2half_rn(s * q);
        }
    }
}

// ---------------- launch -----------------------------------------------------
extern "C" void kernel_launch(void* const* d_in, const int* in_sizes, int n_in,
                              void* d_out, int out_size)
{
    const float* query = (const float*)d_in[0];
    const float* key   = (const float*)d_in[1];
    const float* value = (const float*)d_in[2];
    const float* beta  = (const float*)d_in[3];
    const float* Wq    = (const float*)d_in[4];
    const float* bq    = (const float*)d_in[5];
    const float* Wk    = (const float*)d_in[6];
    const float* bk    = (const float*)d_in[7];
    const float* Wv    = (const float*)d_in[8];
    const float* bv    = (const float*)d_in[9];
    const float* Wb    = (const float*)d_in[10];
    const float* bb    = (const float*)d_in[11];
    const float* Wo    = (const float*)d_in[12];
    const float* bo    = (const float*)d_in[13];
    float* out = (float*)d_out;

    __nv_bfloat16 *pAhi, *pAlo, *pWq16, *pWkh, *pWkl, *pWv16, *pWo16, *pWbh, *pWbl;
    float *pPq, *pPk, *pV, *pB;
    cudaGetSymbolAddress((void**)&pAhi,  g_Ahi);
    cudaGetSymbolAddress((void**)&pAlo,  g_Alo);
    cudaGetSymbolAddress((void**)&pWq16, g_Wq16);
    cudaGetSymbolAddress((void**)&pWkh,  g_Wkhi);
    cudaGetSymbolAddress((void**)&pWkl,  g_Wklo);
    cudaGetSymbolAddress((void**)&pWv16, g_Wv16);
    cudaGetSymbolAddress((void**)&pWo16, g_Wo16);
    cudaGetSymbolAddress((void**)&pWbh,  g_Wbhi);
    cudaGetSymbolAddress((void**)&pWbl,  g_Wblo);
    cudaGetSymbolAddress((void**)&pPq, g_Pq);
    cudaGetSymbolAddress((void**)&pPk, g_Pk);
    cudaGetSymbolAddress((void**)&pV,  g_V);
    cudaGetSymbolAddress((void**)&pB,  g_B);

    const int SMEM_GEMM = 2 * STAGEB;            // 81920 -> 2 CTAs/SM
    const int SMEM_G16  = 2 * STAGE16;           // 40960
    const int SMEM_BETA = BNSTG * BSTAGE;
    cudaFuncSetAttribute(gemm_mma<1>, cudaFuncAttributeMaxDynamicSharedMemorySize, SMEM_GEMM);
    cudaFuncSetAttribute(gemm_f16<0>, cudaFuncAttributeMaxDynamicSharedMemorySize, SMEM_G16);
    cudaFuncSetAttribute(gemm_f16<1>, cudaFuncAttributeMaxDynamicSharedMemorySize, SMEM_G16);
    cudaFuncSetAttribute(beta_mma,    cudaFuncAttributeMaxDynamicSharedMemorySize, SMEM_BETA);

    const int N4A = MROWS * HDIM / 4;
    const int N4W = HDIM * HDIM / 4;
    const int N4B = NHEADS * HDIM / 4;

    const dim3 gBig(8, 64), blk(256);

    // q projection + phi  (1-pass fp16: terminal-multiplier path, amplification ~1)
    conv_half<<<N4A / 256, 256>>>(query, (__half*)pAhi, N4A);
    conv_half<<<N4W / 256, 256>>>(Wq, (__half*)pWq16, N4W);
    gemm_f16<1><<<gBig, blk, SMEM_G16>>>((const __half*)pAhi, (const __half*)pWq16, bq, pPq);
    // k projection + phi  (3-pass bf16: recurrence-amplified path)
    conv_split<<<N4W / 256, 256>>>(Wk, pWkh, pWkl, N4W);
    conv_split<<<N4A / 256, 256>>>(key, pAhi, pAlo, N4A);
    gemm_mma<1><<<gBig, blk, SMEM_GEMM>>>(pAhi, pAlo, pWkh, pWkl, bk, pPk);
    // v projection  (1-pass fp16: linear, non-amplified path)
    conv_half<<<N4A / 256, 256>>>(value, (__half*)pAhi, N4A);
    conv_half<<<N4W / 256, 256>>>(Wv, (__half*)pWv16, N4W);
    gemm_f16<0><<<gBig, blk, SMEM_G16>>>((const __half*)pAhi, (const __half*)pWv16, bv, pV);
    // beta projection + sigmoid  (3-pass bf16)
    conv_split<<<N4A / 256, 256>>>(beta, pAhi, pAlo, N4A);
    conv_split<<<N4B / 256, 256>>>(Wb, pWbh, pWbl, N4B);
    beta_mma<<<MROWS / BROWS, 128, SMEM_BETA>>>(pAhi, pAlo, pWbh, pWbl, bb, pB);
    // scan -> fp16 Y directly into the fp16 GEMM input buffer
    scan_kernel<<<BATCH * NHEADS, 64>>>(pPq, pPk, pV, pB, (__half*)pAhi);
    // output projection  (1-pass fp16: terminal error path)
    conv_half<<<N4W / 256, 256>>>(Wo, (__half*)pWo16, N4W);
    gemm_f16<0><<<gBig, blk, SMEM_G16>>>((const __half*)pAhi, (const __half*)pWo16, bo, out);
}

// round 17
// speedup vs baseline: 4.1616x; 1.0848x over previous
#include <cuda_runtime.h>
#include <cuda_bf16.h>
#include <cuda_fp16.h>
#include <math.h>
#include <stdint.h>

#define BATCH   4
#define SEQ     2048
#define HDIM    1024
#define NHEADS  16
#define MROWS   8192

// ---------------- scratch (device globals; no runtime allocation) -----------
// per-operand activation buffers (enables cross-stream overlap of conversions)
__device__ __half        g_Aq16[(size_t)MROWS * HDIM];   // q fp16; reused as Y by scan
__device__ __nv_bfloat16 g_Akhi[(size_t)MROWS * HDIM];
__device__ __nv_bfloat16 g_Aklo[(size_t)MROWS * HDIM];
__device__ __half        g_Av16[(size_t)MROWS * HDIM];
__device__ __nv_bfloat16 g_Abhi[(size_t)MROWS * HDIM];
__device__ __nv_bfloat16 g_Ablo[(size_t)MROWS * HDIM];
__device__ __half        g_Wq16[(size_t)HDIM * HDIM];
__device__ __nv_bfloat16 g_Wkhi[(size_t)HDIM * HDIM];
__device__ __nv_bfloat16 g_Wklo[(size_t)HDIM * HDIM];
__device__ __half        g_Wv16[(size_t)HDIM * HDIM];
__device__ __half        g_Wo16[(size_t)HDIM * HDIM];
__device__ __nv_bfloat16 g_Wbhi[(size_t)NHEADS * HDIM];
__device__ __nv_bfloat16 g_Wblo[(size_t)NHEADS * HDIM];
__device__ float g_Pq[(size_t)MROWS * HDIM];
__device__ float g_Pk[(size_t)MROWS * HDIM];
__device__ float g_V [(size_t)MROWS * HDIM];
__device__ float g_B [(size_t)MROWS * NHEADS];

// ---------------- baseline-PTX helpers --------------------------------------
__device__ __forceinline__ uint32_t smem_u32(const void* p) {
    uint32_t a;
    asm("{ .reg .u64 t; cvta.to.shared.u64 t, %1; cvt.u32.u64 %0, t; }" : "=r"(a) : "l"(p));
    return a;
}
__device__ __forceinline__ void cp16(uint32_t dst, const void* src) {
    asm volatile("cp.async.cg.shared.global [%0], [%1], 16;\n" :: "r"(dst), "l"(src) : "memory");
}
__device__ __forceinline__ void cp_commit() {
    asm volatile("cp.async.commit_group;\n" ::: "memory");
}
template<int N> __device__ __forceinline__ void cp_wait() {
    asm volatile("cp.async.wait_group %0;\n" :: "n"(N) : "memory");
}
__device__ __forceinline__ void ldsm_x4(uint32_t& r0, uint32_t& r1, uint32_t& r2, uint32_t& r3,
                                        uint32_t addr) {
    asm volatile("ldmatrix.sync.aligned.m8n8.x4.shared.b16 {%0,%1,%2,%3}, [%4];"
                 : "=r"(r0), "=r"(r1), "=r"(r2), "=r"(r3) : "r"(addr));
}
__device__ __forceinline__ void mma_bf16(float* c, const uint32_t* a, const uint32_t* b) {
    asm volatile(
        "mma.sync.aligned.m16n8k16.row.col.f32.bf16.bf16.f32 "
        "{%0,%1,%2,%3}, {%4,%5,%6,%7}, {%8,%9}, {%0,%1,%2,%3};"
        : "+f"(c[0]), "+f"(c[1]), "+f"(c[2]), "+f"(c[3])
        : "r"(a[0]), "r"(a[1]), "r"(a[2]), "r"(a[3]), "r"(b[0]), "r"(b[1]));
}
__device__ __forceinline__ void mma_f16(float* c, const uint32_t* a, const uint32_t* b) {
    asm volatile(
        "mma.sync.aligned.m16n8k16.row.col.f32.f16.f16.f32 "
        "{%0,%1,%2,%3}, {%4,%5,%6,%7}, {%8,%9}, {%0,%1,%2,%3};"
        : "+f"(c[0]), "+f"(c[1]), "+f"(c[2]), "+f"(c[3])
        : "r"(a[0]), "r"(a[1]), "r"(a[2]), "r"(a[3]), "r"(b[0]), "r"(b[1]));
}

// ---------------- conversions (MLP=2: two independent float4 chains) --------
__global__ __launch_bounds__(256)
void conv_split(const float* __restrict__ x, __nv_bfloat16* __restrict__ hi,
                __nv_bfloat16* __restrict__ lo, int n4)
{
    const int half_n = n4 >> 1;
    int i = blockIdx.x * blockDim.x + threadIdx.x;
    if (i >= half_n) return;
#pragma unroll
    for (int p = 0; p < 2; p++) {
        const int j = i + p * half_n;
        float4 v = ((const float4*)x)[j];
        __nv_bfloat16 h0 = __float2bfloat16(v.x);
        __nv_bfloat16 h1 = __float2bfloat16(v.y);
        __nv_bfloat16 h2 = __float2bfloat16(v.z);
        __nv_bfloat16 h3 = __float2bfloat16(v.w);
        __nv_bfloat16 l0 = __float2bfloat16(v.x - __bfloat162float(h0));
        __nv_bfloat16 l1 = __float2bfloat16(v.y - __bfloat162float(h1));
        __nv_bfloat16 l2 = __float2bfloat16(v.z - __bfloat162float(h2));
        __nv_bfloat16 l3 = __float2bfloat16(v.w - __bfloat162float(h3));
        ((__nv_bfloat162*)hi)[2 * j + 0] = __halves2bfloat162(h0, h1);
        ((__nv_bfloat162*)hi)[2 * j + 1] = __halves2bfloat162(h2, h3);
        ((__nv_bfloat162*)lo)[2 * j + 0] = __halves2bfloat162(l0, l1);
        ((__nv_bfloat162*)lo)[2 * j + 1] = __halves2bfloat162(l2, l3);
    }
}

__global__ __launch_bounds__(256)
void conv_half(const float* __restrict__ x, __half* __restrict__ h, int n4)
{
    const int half_n = n4 >> 1;
    int i = blockIdx.x * blockDim.x + threadIdx.x;
    if (i >= half_n) return;
#pragma unroll
    for (int p = 0; p < 2; p++) {
        const int j = i + p * half_n;
        float4 v = ((const float4*)x)[j];
        ((__half2*)h)[2 * j + 0] = __floats2half2_rn(v.x, v.y);
        ((__half2*)h)[2 * j + 1] = __floats2half2_rn(v.z, v.w);
    }
}

// ---------------- epilogues --------------------------------------------------
template<int EPI> __device__ __forceinline__ float epi_f(float x) {
    if (EPI == 1) return x > 0.f ? x + 1.f : expf(x);
    if (EPI == 2) return 1.f / (1.f + expf(-x));
    return x;
}

#define ROWB    80
#define A_PL    (128 * ROWB)
#define STAGEB  (4 * A_PL)          // 40960 (bf16 split: 4 planes)
#define STAGE16 (2 * A_PL)          // 20480 (fp16: 2 planes)
#define KCH     32

// ---------------- split-bf16 HMMA GEMM (3-pass, k path) ---------------------
template<int EPI>
__global__ __launch_bounds__(256, 2)
void gemm_mma(const __nv_bfloat16* __restrict__ Ah, const __nv_bfloat16* __restrict__ Al,
              const __nv_bfloat16* __restrict__ Wh, const __nv_bfloat16* __restrict__ Wl,
              const float* __restrict__ bias, float* __restrict__ C)
{
    extern __shared__ char smem[];
    const uint32_t sb = smem_u32(smem);
    const int tid  = threadIdx.x;
    const int lane = tid & 31;
    const int warp = tid >> 5;
    const int wm   = warp >> 2;
    const int wn   = warp & 3;
    const int m0   = blockIdx.y * 128;
    const int n0   = blockIdx.x * 128;

    auto load_stage = [&](int kc, int st) {
        const int k0 = kc * 32;
        const uint32_t sA = sb + st * STAGEB;
        const uint32_t sB = sA + 2 * A_PL;
#pragma unroll
        for (int i = 0; i < 4; i++) {
            const int idx = tid + i * 256;
            const int pl  = idx >> 9;
            const int r   = (idx >> 2) & 127;
            const int c   = idx & 3;
            cp16(sA + pl * A_PL + r * ROWB + c * 16,
                 (pl ? Al : Ah) + (size_t)(m0 + r) * HDIM + k0 + c * 8);
        }
#pragma unroll
        for (int i = 0; i < 4; i++) {
            const int idx = tid + i * 256;
            const int pl  = idx >> 9;
            const int r   = (idx >> 2) & 127;
            const int c   = idx & 3;
            cp16(sB + pl * A_PL + r * ROWB + c * 16,
                 (pl ? Wl : Wh) + (size_t)(n0 + r) * HDIM + k0 + c * 8);
        }
        cp_commit();
    };

    float acc[4][4][4];
#pragma unroll
    for (int i = 0; i < 4; i++)
#pragma unroll
        for (int j = 0; j < 4; j++)
#pragma unroll
            for (int k = 0; k < 4; k++) acc[i][j][k] = 0.f;

    load_stage(0, 0);

    const uint32_t lrow = lane & 15;
    const uint32_t lcol = (lane >> 4) * 16;

    for (int kc = 0; kc < KCH; kc++) {
        if (kc + 1 < KCH) {
            load_stage(kc + 1, (kc + 1) & 1);
            cp_wait<1>();
        } else {
            cp_wait<0>();
        }
        __syncthreads();

        const uint32_t sA = sb + (kc & 1) * STAGEB;
        const uint32_t sB = sA + 2 * A_PL;

#pragma unroll
        for (int ks = 0; ks < 2; ks++) {
            uint32_t aH[4][4], aL[4][4], b[4][2];
#pragma unroll
            for (int mi = 0; mi < 4; mi++) {
                const uint32_t ra = (wm * 64 + mi * 16 + lrow) * ROWB + ks * 32 + lcol;
                ldsm_x4(aH[mi][0], aH[mi][1], aH[mi][2], aH[mi][3], sA + ra);
                ldsm_x4(aL[mi][0], aL[mi][1], aL[mi][2], aL[mi][3], sA + A_PL + ra);
            }
#pragma unroll
            for (int bq = 0; bq < 2; bq++) {
                uint32_t r0, r1, r2, r3;
                ldsm_x4(r0, r1, r2, r3,
                        sB + (wn * 32 + bq * 16 + lrow) * ROWB + ks * 32 + lcol);
                b[2 * bq + 0][0] = r0; b[2 * bq + 0][1] = r2;
                b[2 * bq + 1][0] = r1; b[2 * bq + 1][1] = r3;
            }
#pragma unroll
            for (int mi = 0; mi < 4; mi++)
#pragma unroll
                for (int ni = 0; ni < 4; ni++) {
                    mma_bf16(acc[mi][ni], aH[mi], b[ni]);
                    mma_bf16(acc[mi][ni], aL[mi], b[ni]);
                }
#pragma unroll
            for (int bq = 0; bq < 2; bq++) {
                uint32_t r0, r1, r2, r3;
                ldsm_x4(r0, r1, r2, r3,
                        sB + A_PL + (wn * 32 + bq * 16 + lrow) * ROWB + ks * 32 + lcol);
                b[2 * bq + 0][0] = r0; b[2 * bq + 0][1] = r2;
                b[2 * bq + 1][0] = r1; b[2 * bq + 1][1] = r3;
            }
#pragma unroll
            for (int mi = 0; mi < 4; mi++)
#pragma unroll
                for (int ni = 0; ni < 4; ni++)
                    mma_bf16(acc[mi][ni], aH[mi], b[ni]);
        }
        if (kc + 1 < KCH) __syncthreads();
    }

#pragma unroll
    for (int mi = 0; mi < 4; mi++) {
#pragma unroll
        for (int ni = 0; ni < 4; ni++) {
            const int r = m0 + wm * 64 + mi * 16 + (lane >> 2);
            const int c = n0 + wn * 32 + ni * 8 + (lane & 3) * 2;
            const float bx = bias[c], by = bias[c + 1];
            float2 o0, o1;
            o0.x = epi_f<EPI>(acc[mi][ni][0] + bx);
            o0.y = epi_f<EPI>(acc[mi][ni][1] + by);
            o1.x = epi_f<EPI>(acc[mi][ni][2] + bx);
            o1.y = epi_f<EPI>(acc[mi][ni][3] + by);
            *(float2*)(C + (size_t)r * HDIM + c)       = o0;
            *(float2*)(C + (size_t)(r + 8) * HDIM + c) = o1;
        }
    }
}

// ---------------- single-pass fp16 HMMA GEMM (q / v / out paths) ------------
template<int EPI>
__global__ __launch_bounds__(256, 2)
void gemm_f16(const __half* __restrict__ A16, const __half* __restrict__ W16,
              const float* __restrict__ bias, float* __restrict__ C)
{
    extern __shared__ char smem[];
    const uint32_t sb = smem_u32(smem);
    const int tid  = threadIdx.x;
    const int lane = tid & 31;
    const int warp = tid >> 5;
    const int wm   = warp >> 2;
    const int wn   = warp & 3;
    const int m0   = blockIdx.y * 128;
    const int n0   = blockIdx.x * 128;

    auto load_stage = [&](int kc, int st) {
        const int k0 = kc * 32;
        const uint32_t sA = sb + st * STAGE16;
        const uint32_t sB = sA + A_PL;
#pragma unroll
        for (int i = 0; i < 2; i++) {
            const int idx = tid + i * 256;
            const int r   = idx >> 2;
            const int c   = idx & 3;
            cp16(sA + r * ROWB + c * 16, A16 + (size_t)(m0 + r) * HDIM + k0 + c * 8);
        }
#pragma unroll
        for (int i = 0; i < 2; i++) {
            const int idx = tid + i * 256;
            const int r   = idx >> 2;
            const int c   = idx & 3;
            cp16(sB + r * ROWB + c * 16, W16 + (size_t)(n0 + r) * HDIM + k0 + c * 8);
        }
        cp_commit();
    };

    float acc[4][4][4];
#pragma unroll
    for (int i = 0; i < 4; i++)
#pragma unroll
        for (int j = 0; j < 4; j++)
#pragma unroll
            for (int k = 0; k < 4; k++) acc[i][j][k] = 0.f;

    load_stage(0, 0);

    const uint32_t lrow = lane & 15;
    const uint32_t lcol = (lane >> 4) * 16;

    for (int kc = 0; kc < KCH; kc++) {
        if (kc + 1 < KCH) {
            load_stage(kc + 1, (kc + 1) & 1);
            cp_wait<1>();
        } else {
            cp_wait<0>();
        }
        __syncthreads();

        const uint32_t sA = sb + (kc & 1) * STAGE16;
        const uint32_t sB = sA + A_PL;

#pragma unroll
        for (int ks = 0; ks < 2; ks++) {
            uint32_t a[4][4], b[4][2];
#pragma unroll
            for (int mi = 0; mi < 4; mi++) {
                const uint32_t ra = (wm * 64 + mi * 16 + lrow) * ROWB + ks * 32 + lcol;
                ldsm_x4(a[mi][0], a[mi][1], a[mi][2], a[mi][3], sA + ra);
            }
#pragma unroll
            for (int bq = 0; bq < 2; bq++) {
                uint32_t r0, r1, r2, r3;
                ldsm_x4(r0, r1, r2, r3,
                        sB + (wn * 32 + bq * 16 + lrow) * ROWB + ks * 32 + lcol);
                b[2 * bq + 0][0] = r0; b[2 * bq + 0][1] = r2;
                b[2 * bq + 1][0] = r1; b[2 * bq + 1][1] = r3;
            }
#pragma unroll
            for (int mi = 0; mi < 4; mi++)
#pragma unroll
                for (int ni = 0; ni < 4; ni++)
                    mma_f16(acc[mi][ni], a[mi], b[ni]);
        }
        if (kc + 1 < KCH) __syncthreads();
    }

#pragma unroll
    for (int mi = 0; mi < 4; mi++) {
#pragma unroll
        for (int ni = 0; ni < 4; ni++) {
            const int r = m0 + wm * 64 + mi * 16 + (lane >> 2);
            const int c = n0 + wn * 32 + ni * 8 + (lane & 3) * 2;
            const float bx = bias[c], by = bias[c + 1];
            float2 o0, o1;
            o0.x = epi_f<EPI>(acc[mi][ni][0] + bx);
            o0.y = epi_f<EPI>(acc[mi][ni][1] + by);
            o1.x = epi_f<EPI>(acc[mi][ni][2] + bx);
            o1.y = epi_f<EPI>(acc[mi][ni][3] + by);
            *(float2*)(C + (size_t)r * HDIM + c)       = o0;
            *(float2*)(C + (size_t)(r + 8) * HDIM + c) = o1;
        }
    }
}

// ---------------- beta projection: sigmoid(A @ Wb^T + bb), N=16 -------------
#define BROWS  64
#define BSTA   (BROWS * ROWB)
#define BSTB   (16 * ROWB)
#define BSTAGE (BSTA + BSTB)
#define BKTOT  96
#define BNSTG  3

__global__ __launch_bounds__(128, 4)
void beta_mma(const __nv_bfloat16* __restrict__ Ah, const __nv_bfloat16* __restrict__ Al,
              const __nv_bfloat16* __restrict__ Wh, const __nv_bfloat16* __restrict__ Wl,
              const float* __restrict__ bb, float* __restrict__ Bout)
{
    extern __shared__ char smem[];
    const uint32_t sb = smem_u32(smem);
    const int tid  = threadIdx.x;
    const int lane = tid & 31;
    const int warp = tid >> 5;
    const int m0   = blockIdx.x * BROWS;

    auto load_stage = [&](int kc, int st) {
        const int ph = kc >> 5;
        const __nv_bfloat16* As = (ph == 1) ? Al : Ah;
        const __nv_bfloat16* Ws = (ph == 2) ? Wl : Wh;
        const int k0 = (kc & 31) * 32;
        const uint32_t sA = sb + st * BSTAGE;
        const uint32_t sB = sA + BSTA;
#pragma unroll
        for (int i = 0; i < 2; i++) {
            const int idx = tid + i * 128;
            const int row = idx >> 2, c = idx & 3;
            cp16(sA + row * ROWB + c * 16, As + (size_t)(m0 + row) * HDIM + k0 + c * 8);
        }
        if (tid < 64) {
            const int row = tid >> 2, c = tid & 3;
            cp16(sB + row * ROWB + c * 16, Ws + (size_t)row * HDIM + k0 + c * 8);
        }
        cp_commit();
    };

    float acc[2][4];
#pragma unroll
    for (int i = 0; i < 2; i++)
#pragma unroll
        for (int k = 0; k < 4; k++) acc[i][k] = 0.f;

    load_stage(0, 0);
    load_stage(1, 1);

    for (int kc = 0; kc < BKTOT; kc++) {
        cp_wait<1>();
        __syncthreads();
        if (kc + 2 < BKTOT) load_stage(kc + 2, (kc + 2) % BNSTG);
        else                cp_commit();

        const uint32_t sA = sb + (kc % BNSTG) * BSTAGE;
        const uint32_t sB = sA + BSTA;
        const uint32_t lrow = lane & 15;
        const uint32_t lcol = (lane >> 4) * 16;

#pragma unroll
        for (int ks = 0; ks < 2; ks++) {
            uint32_t a[4], b[2][2];
            ldsm_x4(a[0], a[1], a[2], a[3],
                    sA + (warp * 16 + lrow) * ROWB + ks * 32 + lcol);
            uint32_t r0, r1, r2, r3;
            ldsm_x4(r0, r1, r2, r3, sB + lrow * ROWB + ks * 32 + lcol);
            b[0][0] = r0; b[0][1] = r2;
            b[1][0] = r1; b[1][1] = r3;
            mma_bf16(acc[0], a, b[0]);
            mma_bf16(acc[1], a, b[1]);
        }
    }

#pragma unroll
    for (int ni = 0; ni < 2; ni++) {
        const int r = m0 + warp * 16 + (lane >> 2);
        const int c = ni * 8 + (lane & 3) * 2;
        const float bx = bb[c], by = bb[c + 1];
        float2 o0, o1;
        o0.x = 1.f / (1.f + expf(-(acc[ni][0] + bx)));
        o0.y = 1.f / (1.f + expf(-(acc[ni][1] + by)));
        o1.x = 1.f / (1.f + expf(-(acc[ni][2] + bx)));
        o1.y = 1.f / (1.f + expf(-(acc[ni][3] + by)));
        *(float2*)(Bout + (size_t)r * NHEADS + c)       = o0;
        *(float2*)(Bout + (size_t)(r + 8) * NHEADS + c) = o1;
    }
}

// ---------------- delta-rule diagonal scan: s <- a*s + c --------------------
__global__ __launch_bounds__(64)
void scan_kernel(const float* __restrict__ Pq, const float* __restrict__ Pk,
                 const float* __restrict__ Vb, const float* __restrict__ Bs,
                 __half* __restrict__ Yh)
{
    const int bh = blockIdx.x;
    const int d  = threadIdx.x;
    const size_t base = (size_t)(bh >> 4) * SEQ * HDIM + (size_t)(bh & 15) * 64 + d;
    const float* pk = Pk + base;
    const float* pq = Pq + base;
    const float* vv = Vb + base;
    __half* yh = Yh + base;
    const float* bp = Bs + (size_t)(bh >> 4) * SEQ * NHEADS + (bh & 15);

    float rpk[16], rpq[16], rv[16], rb[16];
#pragma unroll
    for (int j = 0; j < 16; j++) {
        const size_t o = (size_t)j * HDIM;
        rpk[j] = pk[o]; rpq[j] = pq[o]; rv[j] = vv[o];
        rb[j]  = bp[(size_t)j * NHEADS];
    }

    float s = 0.f;
    for (int t0 = 0; t0 < SEQ; t0 += 16) {
#pragma unroll
        for (int j = 0; j < 16; j++) {
            const int t = t0 + j;
            const float a = 1.f - rb[j] * rpk[j] * rpk[j];
            const float c = rb[j] * rv[j] * rpk[j];
            const float q = rpq[j];
            const int tn = t + 16;
            if (tn < SEQ) {
                const size_t o = (size_t)tn * HDIM;
                rpk[j] = pk[o]; rpq[j] = pq[o]; rv[j] = vv[o];
                rb[j]  = bp[(size_t)tn * NHEADS];
            }
            s = fmaf(a, s, c);
            yh[(size_t)t * HDIM] = __float2half_rn(s * q);
        }
    }
}

// ---------------- launch -----------------------------------------------------
extern "C" void kernel_launch(void* const* d_in, const int* in_sizes, int n_in,
                              void* d_out, int out_size)
{
    const float* query = (const float*)d_in[0];
    const float* key   = (const float*)d_in[1];
    const float* value = (const float*)d_in[2];
    const float* beta  = (const float*)d_in[3];
    const float* Wq    = (const float*)d_in[4];
    const float* bq    = (const float*)d_in[5];
    const float* Wk    = (const float*)d_in[6];
    const float* bk    = (const float*)d_in[7];
    const float* Wv    = (const float*)d_in[8];
    const float* bv    = (const float*)d_in[9];
    const float* Wb    = (const float*)d_in[10];
    const float* bb    = (const float*)d_in[11];
    const float* Wo    = (const float*)d_in[12];
    const float* bo    = (const float*)d_in[13];
    float* out = (float*)d_out;

    __half *pAq16, *pAv16, *pWq16, *pWv16, *pWo16;
    __nv_bfloat16 *pAkh, *pAkl, *pAbh, *pAbl, *pWkh, *pWkl, *pWbh, *pWbl;
    float *pPq, *pPk, *pV, *pB;
    cudaGetSymbolAddress((void**)&pAq16, g_Aq16);
    cudaGetSymbolAddress((void**)&pAkh,  g_Akhi);
    cudaGetSymbolAddress((void**)&pAkl,  g_Aklo);
    cudaGetSymbolAddress((void**)&pAv16, g_Av16);
    cudaGetSymbolAddress((void**)&pAbh,  g_Abhi);
    cudaGetSymbolAddress((void**)&pAbl,  g_Ablo);
    cudaGetSymbolAddress((void**)&pWq16, g_Wq16);
    cudaGetSymbolAddress((void**)&pWkh,  g_Wkhi);
    cudaGetSymbolAddress((void**)&pWkl,  g_Wklo);
    cudaGetSymbolAddress((void**)&pWv16, g_Wv16);
    cudaGetSymbolAddress((void**)&pWo16, g_Wo16);
    cudaGetSymbolAddress((void**)&pWbh,  g_Wbhi);
    cudaGetSymbolAddress((void**)&pWbl,  g_Wblo);
    cudaGetSymbolAddress((void**)&pPq, g_Pq);
    cudaGetSymbolAddress((void**)&pPk, g_Pk);
    cudaGetSymbolAddress((void**)&pV,  g_V);
    cudaGetSymbolAddress((void**)&pB,  g_B);

    const int SMEM_GEMM = 2 * STAGEB;            // 81920 -> 2 CTAs/SM
    const int SMEM_G16  = 2 * STAGE16;           // 40960
    const int SMEM_BETA = BNSTG * BSTAGE;
    cudaFuncSetAttribute(gemm_mma<1>, cudaFuncAttributeMaxDynamicSharedMemorySize, SMEM_GEMM);
    cudaFuncSetAttribute(gemm_f16<0>, cudaFuncAttributeMaxDynamicSharedMemorySize, SMEM_G16);
    cudaFuncSetAttribute(gemm_f16<1>, cudaFuncAttributeMaxDynamicSharedMemorySize, SMEM_G16);
    cudaFuncSetAttribute(beta_mma,    cudaFuncAttributeMaxDynamicSharedMemorySize, SMEM_BETA);

    const int N4A = MROWS * HDIM / 4;
    const int N4W = HDIM * HDIM / 4;
    const int N4B = NHEADS * HDIM / 4;
    const int GA  = N4A / 2 / 256;   // MLP=2 conv grids
    const int GW  = N4W / 2 / 256;
    const int GB  = N4B / 2 / 256;

    const dim3 gBig(8, 64), blk(256);

    // fork a second stream into the capture graph (created per call; the
    // harness only invokes this a handful of times outside replay)
    cudaStream_t s2;
    cudaStreamCreateWithFlags(&s2, cudaStreamNonBlocking);
    cudaEvent_t evFork, evK, evV, evB, evO;
    cudaEventCreateWithFlags(&evFork, cudaEventDisableTiming);
    cudaEventCreateWithFlags(&evK,    cudaEventDisableTiming);
    cudaEventCreateWithFlags(&evV,    cudaEventDisableTiming);
    cudaEventCreateWithFlags(&evB,    cudaEventDisableTiming);
    cudaEventCreateWithFlags(&evO,    cudaEventDisableTiming);

    cudaEventRecord(evFork, 0);
    cudaStreamWaitEvent(s2, evFork, 0);

    // ---- side stream: all conversions independent of GPU results ----
    conv_split<<<GW, 256, 0, s2>>>(Wk, pWkh, pWkl, N4W);
    conv_split<<<GA, 256, 0, s2>>>(key, pAkh, pAkl, N4A);
    cudaEventRecord(evK, s2);
    conv_half<<<GW, 256, 0, s2>>>(Wv, (__half*)pWv16, N4W);
    conv_half<<<GA, 256, 0, s2>>>(value, (__half*)pAv16, N4A);
    cudaEventRecord(evV, s2);
    conv_split<<<GA, 256, 0, s2>>>(beta, pAbh, pAbl, N4A);
    conv_split<<<GB, 256, 0, s2>>>(Wb, pWbh, pWbl, N4B);
    beta_mma<<<MROWS / BROWS, 128, SMEM_BETA, s2>>>(pAbh, pAbl, pWbh, pWbl, bb, pB);
    cudaEventRecord(evB, s2);
    conv_half<<<GW, 256, 0, s2>>>(Wo, (__half*)pWo16, N4W);
    cudaEventRecord(evO, s2);

    // ---- main stream: critical path ----
    // q projection + phi (1-pass fp16)
    conv_half<<<GA, 256>>>(query, (__half*)pAq16, N4A);
    conv_half<<<GW, 256>>>(Wq, (__half*)pWq16, N4W);
    gemm_f16<1><<<gBig, blk, SMEM_G16>>>((const __half*)pAq16, (const __half*)pWq16, bq, pPq);
    // k projection + phi (3-pass bf16)
    cudaStreamWaitEvent(0, evK, 0);
    gemm_mma<1><<<gBig, blk, SMEM_GEMM>>>(pAkh, pAkl, pWkh, pWkl, bk, pPk);
    // v projection (1-pass fp16)
    cudaStreamWaitEvent(0, evV, 0);
    gemm_f16<0><<<gBig, blk, SMEM_G16>>>((const __half*)pAv16, (const __half*)pWv16, bv, pV);
    // scan (needs B from side stream) -> fp16 Y into g_Aq16 (free after GEMMq)
    cudaStreamWaitEvent(0, evB, 0);
    scan_kernel<<<BATCH * NHEADS, 64>>>(pPq, pPk, pV, pB, (__half*)pAq16);
    // output projection (1-pass fp16)
    cudaStreamWaitEvent(0, evO, 0);
    gemm_f16<0><<<gBig, blk, SMEM_G16>>>((const __half*)pAq16, (const __half*)pWo16, bo, out);
}